// round 7
// baseline (speedup 1.0000x reference)
#include <cuda_runtime.h>
#include <cuda_fp16.h>
#include <math.h>
#include <stdint.h>

#define DIM  1024
#define NEXP 8
#define NTOK 16384
#define BM   128
#define BN   256
#define BK   32
#define KIT  (DIM/BK)        // 32 stages
#define ROWB 80              // bytes per smem row (32 halves data + 16 pad)
// stage layout: Ah(128) | Al(128) | Bh(256) | Bl(256) rows
#define OFF_AH 0
#define OFF_AL (128*ROWB)          // 10240
#define OFF_BH (256*ROWB)          // 20480
#define OFF_BL (OFF_BH + 256*ROWB) // 40960
#define STGB   (OFF_BL + 256*ROWB) // 61440
#define NSTG 3
#define SMEM_BYTES (NSTG*STGB)     // 184320

// ---------------- device-global scratch (allocation-free) ----------------
__device__ __half g_Xh[(size_t)NTOK * DIM];
__device__ __half g_Xl[(size_t)NTOK * DIM];   // unscaled residual
__device__ __half g_Wh[(size_t)(1 + NEXP) * DIM * DIM];   // [N][K], W*64
__device__ __half g_Wl[(size_t)(1 + NEXP) * DIM * DIM];   // unscaled residual of W*64
__device__ float  g_logits[(size_t)NTOK * DIM];
__device__ int    g_cnt[NEXP];
__device__ int    g_tok[NEXP * NTOK];
__device__ float  g_p[NTOK];

// ---------------- PTX helpers ----------------
static __device__ __forceinline__ uint32_t smem_u32(const void* p) {
    uint32_t a;
    asm("{ .reg .u64 t; cvta.to.shared.u64 t, %1; cvt.u32.u64 %0, t; }" : "=r"(a) : "l"(p));
    return a;
}
#define CP_ASYNC16(dst, src, sz) \
    asm volatile("cp.async.cg.shared.global [%0], [%1], 16, %2;" \
                 :: "r"(dst), "l"(src), "r"(sz) : "memory")
#define CP_COMMIT() asm volatile("cp.async.commit_group;" ::: "memory")
#define CP_WAIT_1() asm volatile("cp.async.wait_group 1;" ::: "memory")

#define LDM_X4(r, addr) \
    asm volatile("ldmatrix.sync.aligned.m8n8.x4.shared.b16 {%0,%1,%2,%3}, [%4];" \
                 : "=r"((r)[0]), "=r"((r)[1]), "=r"((r)[2]), "=r"((r)[3]) : "r"(addr))

#define MMA(d, a, b0_, b1_) \
    asm volatile("mma.sync.aligned.m16n8k16.row.col.f32.f16.f16.f32 " \
                 "{%0,%1,%2,%3},{%4,%5,%6,%7},{%8,%9},{%0,%1,%2,%3};" \
                 : "+f"((d)[0]), "+f"((d)[1]), "+f"((d)[2]), "+f"((d)[3]) \
                 : "r"((a)[0]), "r"((a)[1]), "r"((a)[2]), "r"((a)[3]), \
                   "r"(b0_), "r"(b1_))

// =====================================================================
__global__ void k_init() {
    if (threadIdx.x < NEXP) g_cnt[threadIdx.x] = 0;
}

// Split x into (h, residual) fp16 pairs (UNscaled residual).
__global__ __launch_bounds__(256) void k_split_x(const float* __restrict__ X) {
    const size_t i = (size_t)blockIdx.x * 256 + threadIdx.x;   // float4 index
    float4 v = ((const float4*)X)[i];
    __half h0 = __float2half_rn(v.x), h1 = __float2half_rn(v.y);
    __half h2 = __float2half_rn(v.z), h3 = __float2half_rn(v.w);
    __half l0 = __float2half_rn(v.x - __half2float(h0));
    __half l1 = __float2half_rn(v.y - __half2float(h1));
    __half l2 = __float2half_rn(v.z - __half2float(h2));
    __half l3 = __float2half_rn(v.w - __half2float(h3));
    ((__half2*)g_Xh)[2 * i]     = __halves2half2(h0, h1);
    ((__half2*)g_Xh)[2 * i + 1] = __halves2half2(h2, h3);
    ((__half2*)g_Xl)[2 * i]     = __halves2half2(l0, l1);
    ((__half2*)g_Xl)[2 * i + 1] = __halves2half2(l2, l3);
}

// Transpose W ([K][N] -> [N][K]), scale x64, split to fp16 (h, residual).
__global__ __launch_bounds__(256) void k_split_w(const float* __restrict__ Wg,
                                                 const float* __restrict__ We) {
    __shared__ float t[32][33];
    const int z = blockIdx.z;
    const float* src = (z == 0) ? Wg : (We + (size_t)(z - 1) * DIM * DIM);
    __half* dh = g_Wh + (size_t)z * DIM * DIM;
    __half* dl = g_Wl + (size_t)z * DIM * DIM;
    const int x = blockIdx.x * 32 + threadIdx.x;
    const int y0 = blockIdx.y * 32 + threadIdx.y;
    #pragma unroll
    for (int i = 0; i < 32; i += 8)
        t[threadIdx.y + i][threadIdx.x] = src[(size_t)(y0 + i) * DIM + x];
    __syncthreads();
    const int x2 = blockIdx.y * 32 + threadIdx.x;
    const int y2 = blockIdx.x * 32 + threadIdx.y;
    #pragma unroll
    for (int i = 0; i < 32; i += 8) {
        float w6 = t[threadIdx.x][threadIdx.y + i] * 64.f;
        __half h = __float2half_rn(w6);
        __half l = __float2half_rn(w6 - __half2float(h));
        dh[(size_t)(y2 + i) * DIM + x2] = h;
        dl[(size_t)(y2 + i) * DIM + x2] = l;
    }
}

// =====================================================================
// GEMM via mma.sync fp16 split-precision, SINGLE fp32 accumulator.
// 512 threads = 16 warps as 4(m) x 4(n); warp tile 32x64; block 128x256.
// 3-stage cp.async pipeline, one __syncthreads per stage.
// MODE 0: gating  -> logits = x@Wg + bg
// MODE 1: expert  -> out = relu(x@We[e] + be[e]) * p   (rows gathered)
// =====================================================================
template <int MODE>
__global__ __launch_bounds__(512, 1) void k_gemm(const float* __restrict__ bias_,
                                                 float* __restrict__ C) {
    extern __shared__ char smem[];
    __shared__ int stok[BM];

    const int tid = threadIdx.x;
    const int lane = tid & 31;
    const int w = tid >> 5;
    const int mbase = blockIdx.y * BM;
    const int nbase = blockIdx.x * BN;

    int e = 0;
    const float* bias = bias_;
    size_t woff = 0;
    if (MODE == 1) {
        e = blockIdx.z;
        const int cnt = g_cnt[e];
        if (mbase >= cnt) return;
        woff = (size_t)(1 + e) * DIM * DIM;
        bias = bias_ + e * DIM;
        if (tid < BM) {
            const int i = mbase + tid;
            stok[tid] = (i < cnt) ? g_tok[e * NTOK + i] : -1;
        }
    } else {
        if (tid < BM) stok[tid] = mbase + tid;
    }
    __syncthreads();

    const uint32_t sb = smem_u32(smem);

    // ---- cp.async jobs: up to 2 rows per thread
    // tid<128:       job0 = Ah row tid,        job1 = Bl row tid
    // tid in 128..255: job0 = Al row tid-128,  job1 = Bl row tid
    // tid in 256..511: job0 = Bh row tid-256,  (no job1)
    const __half* gp0;
    const __half* gp1 = nullptr;
    uint32_t sz0 = 16u, sz1 = 16u;
    uint32_t so0, so1 = 0;
    if (tid < 256) {
        const int r = tid & 127;
        const int tok = stok[r];
        sz0 = (tok >= 0) ? 16u : 0u;
        const __half* base = (tid < 128) ? g_Xh : g_Xl;
        gp0 = base + (size_t)(tok >= 0 ? tok : 0) * DIM;
        so0 = ((tid < 128) ? OFF_AH : OFF_AL) + r * ROWB;
        gp1 = g_Wl + woff + (size_t)(nbase + tid) * DIM;
        so1 = OFF_BL + tid * ROWB;
    } else {
        const int r = tid - 256;
        gp0 = g_Wh + woff + (size_t)(nbase + r) * DIM;
        so0 = OFF_BH + r * ROWB;
    }

    // ---- warp tiling: 16 warps as 4(m) x 4(n); warp tile 32x64
    const int wm = (w & 3) * 32;
    const int wn = (w >> 2) * 64;
    const int lr = lane & 15;
    const int lkb = (lane >> 4) * 16;   // k-half byte offset for ldmatrix

    float acc[2][8][4];
    #pragma unroll
    for (int mi = 0; mi < 2; ++mi)
        #pragma unroll
        for (int nj = 0; nj < 8; ++nj)
            #pragma unroll
            for (int q = 0; q < 4; ++q) acc[mi][nj][q] = 0.f;

    // prologue: stages 0 and 1
    #pragma unroll
    for (int s = 0; s < 2; ++s) {
        const uint32_t d = sb + s * STGB;
        #pragma unroll
        for (int q = 0; q < 4; ++q)
            CP_ASYNC16(d + so0 + q * 16, (const char*)(gp0 + s * BK) + q * 16, sz0);
        if (tid < 256) {
            #pragma unroll
            for (int q = 0; q < 4; ++q)
                CP_ASYNC16(d + so1 + q * 16, (const char*)(gp1 + s * BK) + q * 16, sz1);
        }
        CP_COMMIT();
    }

    int rd = 0, wr = 2;   // rotating slot indices (mod 3)
    for (int it = 0; it < KIT; ++it) {
        CP_WAIT_1();            // stage `it` complete (stage it+1 may be in flight)
        __syncthreads();        // all warps done reading slot `wr`

        if (it + 2 < KIT) {     // issue loads for stage it+2 into slot wr
            const uint32_t d = sb + wr * STGB;
            const int k0 = (it + 2) * BK;
            #pragma unroll
            for (int q = 0; q < 4; ++q)
                CP_ASYNC16(d + so0 + q * 16, (const char*)(gp0 + k0) + q * 16, sz0);
            if (tid < 256) {
                #pragma unroll
                for (int q = 0; q < 4; ++q)
                    CP_ASYNC16(d + so1 + q * 16, (const char*)(gp1 + k0) + q * 16, sz1);
            }
        }
        CP_COMMIT();            // uniform group accounting

        const uint32_t sgb = sb + rd * STGB;
        #pragma unroll
        for (int kk = 0; kk < 2; ++kk) {       // two k16 steps in BK=32
            const uint32_t kb = kk * 32 + lkb;
            uint32_t ah[2][4], al[2][4];
            #pragma unroll
            for (int mi = 0; mi < 2; ++mi) {
                const uint32_t ro = (uint32_t)(wm + mi * 16 + lr) * ROWB + kb;
                LDM_X4(ah[mi], sgb + OFF_AH + ro);
                LDM_X4(al[mi], sgb + OFF_AL + ro);
            }
            #pragma unroll
            for (int njp = 0; njp < 4; ++njp) {
                uint32_t bh[4], bl[4];
                const uint32_t ro = (uint32_t)(wn + njp * 16 + lr) * ROWB + kb;
                LDM_X4(bh, sgb + OFF_BH + ro);
                LDM_X4(bl, sgb + OFF_BL + ro);
                // pass 1: ah*bh (4 independent)
                #pragma unroll
                for (int mi = 0; mi < 2; ++mi)
                    #pragma unroll
                    for (int t = 0; t < 2; ++t)
                        MMA(acc[mi][njp * 2 + t], ah[mi], bh[t], bh[t + 2]);
                // pass 2: ah*bl (4 independent)
                #pragma unroll
                for (int mi = 0; mi < 2; ++mi)
                    #pragma unroll
                    for (int t = 0; t < 2; ++t)
                        MMA(acc[mi][njp * 2 + t], ah[mi], bl[t], bl[t + 2]);
                // pass 3: al*bh (chains separated by 4 MMAs)
                #pragma unroll
                for (int mi = 0; mi < 2; ++mi)
                    #pragma unroll
                    for (int t = 0; t < 2; ++t)
                        MMA(acc[mi][njp * 2 + t], al[mi], bh[t], bh[t + 2]);
            }
        }
        rd = (rd == 2) ? 0 : rd + 1;
        wr = (wr == 2) ? 0 : wr + 1;
    }

    // ---- epilogue: result is 64*(x@W); scale by 1/64, add bias ----
    const int gid = lane >> 2;
    const int tq = lane & 3;
    #pragma unroll
    for (int mi = 0; mi < 2; ++mi) {
        #pragma unroll
        for (int rh = 0; rh < 2; ++rh) {
            const int mloc = wm + mi * 16 + gid + rh * 8;
            const int tok = stok[mloc];
            if (MODE == 1 && tok < 0) continue;
            const float pt = (MODE == 1) ? g_p[tok] : 1.f;
            float* dst = C + (size_t)tok * DIM;
            #pragma unroll
            for (int nj = 0; nj < 8; ++nj) {
                const int n = nbase + wn + nj * 8 + tq * 2;
                float v0 = acc[mi][nj][rh * 2]     * (1.f / 64.f) + bias[n];
                float v1 = acc[mi][nj][rh * 2 + 1] * (1.f / 64.f) + bias[n + 1];
                if (MODE == 1) {
                    v0 = fmaxf(v0, 0.f) * pt;
                    v1 = fmaxf(v1, 0.f) * pt;
                }
                *(float2*)(dst + n) = make_float2(v0, v1);
            }
        }
    }
}

// =====================================================================
// Routing: 1 block per token; argmax (first-index tie-break) + 1/sum(exp)
// =====================================================================
__global__ __launch_bounds__(256) void k_route() {
    const int t = blockIdx.x;
    const int tid = threadIdx.x;
    const float* row = g_logits + (size_t)t * DIM;

    float4 v = ((const float4*)row)[tid];

    float m = v.x; int mi = tid * 4;
    if (v.y > m) { m = v.y; mi = tid * 4 + 1; }
    if (v.z > m) { m = v.z; mi = tid * 4 + 2; }
    if (v.w > m) { m = v.w; mi = tid * 4 + 3; }

    #pragma unroll
    for (int off = 16; off > 0; off >>= 1) {
        float om = __shfl_down_sync(0xffffffffu, m, off);
        int   oi = __shfl_down_sync(0xffffffffu, mi, off);
        if (om > m || (om == m && oi < mi)) { m = om; mi = oi; }
    }

    __shared__ float sm[8];
    __shared__ int   si[8];
    __shared__ float smax;
    __shared__ int   sarg;

    const int wid = tid >> 5, lane = tid & 31;
    if (lane == 0) { sm[wid] = m; si[wid] = mi; }
    __syncthreads();
    if (tid == 0) {
        float bm_ = sm[0]; int bi = si[0];
        #pragma unroll
        for (int w = 1; w < 8; w++)
            if (sm[w] > bm_ || (sm[w] == bm_ && si[w] < bi)) { bm_ = sm[w]; bi = si[w]; }
        smax = bm_; sarg = bi;
    }
    __syncthreads();

    const float mx = smax;
    float s = expf(v.x - mx) + expf(v.y - mx) + expf(v.z - mx) + expf(v.w - mx);
    #pragma unroll
    for (int off = 16; off > 0; off >>= 1)
        s += __shfl_down_sync(0xffffffffu, s, off);
    if (lane == 0) sm[wid] = s;
    __syncthreads();
    if (tid == 0) {
        float tot = 0.f;
        #pragma unroll
        for (int w = 0; w < 8; w++) tot += sm[w];
        const int ex = sarg & (NEXP - 1);
        const int pos = atomicAdd(&g_cnt[ex], 1);
        g_tok[ex * NTOK + pos] = t;
        g_p[t] = 1.f / tot;
    }
}

// =====================================================================
extern "C" void kernel_launch(void* const* d_in, const int* in_sizes, int n_in,
                              void* d_out, int out_size) {
    const float* x  = (const float*)d_in[0];
    const float* Wg = (const float*)d_in[1];
    const float* bg = (const float*)d_in[2];
    const float* We = (const float*)d_in[3];
    const float* be = (const float*)d_in[4];
    float* out = (float*)d_out;

    float* logits;
    cudaGetSymbolAddress((void**)&logits, g_logits);

    cudaFuncSetAttribute(k_gemm<0>, cudaFuncAttributeMaxDynamicSharedMemorySize, SMEM_BYTES);
    cudaFuncSetAttribute(k_gemm<1>, cudaFuncAttributeMaxDynamicSharedMemorySize, SMEM_BYTES);

    k_init<<<1, 32>>>();
    k_split_x<<<(NTOK * DIM / 4) / 256, 256>>>(x);
    k_split_w<<<dim3(32, 32, 1 + NEXP), dim3(32, 8)>>>(Wg, We);
    k_gemm<0><<<dim3(DIM / BN, NTOK / BM), 512, SMEM_BYTES>>>(bg, logits);
    k_route<<<NTOK, 256>>>();
    k_gemm<1><<<dim3(DIM / BN, NTOK / BM, NEXP), 512, SMEM_BYTES>>>(be, out);
}

// round 8
// speedup vs baseline: 1.1321x; 1.1321x over previous
#include <cuda_runtime.h>
#include <cuda_fp16.h>
#include <math.h>
#include <stdint.h>

#define DIM  1024
#define NEXP 8
#define NTOK 16384
#define BM   128
#define BN   256
#define BK   32
#define KIT  (DIM/BK)        // 32 stages
#define ROWB 80              // bytes per smem row (32 halves data + 16 pad)
// stage layout: Ah(128) | Al(128) | Bh(256) | Bl(256) rows
#define OFF_AH 0
#define OFF_AL (128*ROWB)
#define OFF_BH (256*ROWB)
#define OFF_BL (OFF_BH + 256*ROWB)
#define STGB   (OFF_BL + 256*ROWB) // 61440
#define NSTG 3
#define SMEM_BYTES (NSTG*STGB)     // 184320

// ---------------- device-global scratch (allocation-free) ----------------
__device__ __half g_Xh[(size_t)NTOK * DIM];
__device__ __half g_Xl[(size_t)NTOK * DIM];   // unscaled residual
__device__ __half g_Wh[(size_t)(1 + NEXP) * DIM * DIM];   // [N][K], W*64
__device__ __half g_Wl[(size_t)(1 + NEXP) * DIM * DIM];   // unscaled residual of W*64
__device__ float  g_logits[(size_t)NTOK * DIM];
__device__ int    g_cnt[NEXP];
__device__ int    g_tok[NEXP * NTOK];
__device__ float  g_p[NTOK];

// ---------------- PTX helpers ----------------
static __device__ __forceinline__ uint32_t smem_u32(const void* p) {
    uint32_t a;
    asm("{ .reg .u64 t; cvta.to.shared.u64 t, %1; cvt.u32.u64 %0, t; }" : "=r"(a) : "l"(p));
    return a;
}
#define CP_ASYNC16(dst, src, sz) \
    asm volatile("cp.async.cg.shared.global [%0], [%1], 16, %2;" \
                 :: "r"(dst), "l"(src), "r"(sz) : "memory")
#define CP_COMMIT() asm volatile("cp.async.commit_group;" ::: "memory")
#define CP_WAIT_1() asm volatile("cp.async.wait_group 1;" ::: "memory")

// volatile: prevents CSE of the pass-3 bh reload (would otherwise keep 16 regs live)
#define LDM_X4(r, addr) \
    asm volatile("ldmatrix.sync.aligned.m8n8.x4.shared.b16 {%0,%1,%2,%3}, [%4];" \
                 : "=r"((r)[0]), "=r"((r)[1]), "=r"((r)[2]), "=r"((r)[3]) : "r"(addr))

#define MMA(d, a, b0_, b1_) \
    asm volatile("mma.sync.aligned.m16n8k16.row.col.f32.f16.f16.f32 " \
                 "{%0,%1,%2,%3},{%4,%5,%6,%7},{%8,%9},{%0,%1,%2,%3};" \
                 : "+f"((d)[0]), "+f"((d)[1]), "+f"((d)[2]), "+f"((d)[3]) \
                 : "r"((a)[0]), "r"((a)[1]), "r"((a)[2]), "r"((a)[3]), \
                   "r"(b0_), "r"(b1_))

// =====================================================================
__global__ void k_init() {
    if (threadIdx.x < NEXP) g_cnt[threadIdx.x] = 0;
}

// Split x into (h, residual) fp16 pairs (UNscaled residual).
__global__ __launch_bounds__(256) void k_split_x(const float* __restrict__ X) {
    const size_t i = (size_t)blockIdx.x * 256 + threadIdx.x;   // float4 index
    float4 v = ((const float4*)X)[i];
    __half h0 = __float2half_rn(v.x), h1 = __float2half_rn(v.y);
    __half h2 = __float2half_rn(v.z), h3 = __float2half_rn(v.w);
    __half l0 = __float2half_rn(v.x - __half2float(h0));
    __half l1 = __float2half_rn(v.y - __half2float(h1));
    __half l2 = __float2half_rn(v.z - __half2float(h2));
    __half l3 = __float2half_rn(v.w - __half2float(h3));
    ((__half2*)g_Xh)[2 * i]     = __halves2half2(h0, h1);
    ((__half2*)g_Xh)[2 * i + 1] = __halves2half2(h2, h3);
    ((__half2*)g_Xl)[2 * i]     = __halves2half2(l0, l1);
    ((__half2*)g_Xl)[2 * i + 1] = __halves2half2(l2, l3);
}

// Transpose W ([K][N] -> [N][K]), scale x64, split to fp16 (h, residual).
__global__ __launch_bounds__(256) void k_split_w(const float* __restrict__ Wg,
                                                 const float* __restrict__ We) {
    __shared__ float t[32][33];
    const int z = blockIdx.z;
    const float* src = (z == 0) ? Wg : (We + (size_t)(z - 1) * DIM * DIM);
    __half* dh = g_Wh + (size_t)z * DIM * DIM;
    __half* dl = g_Wl + (size_t)z * DIM * DIM;
    const int x = blockIdx.x * 32 + threadIdx.x;
    const int y0 = blockIdx.y * 32 + threadIdx.y;
    #pragma unroll
    for (int i = 0; i < 32; i += 8)
        t[threadIdx.y + i][threadIdx.x] = src[(size_t)(y0 + i) * DIM + x];
    __syncthreads();
    const int x2 = blockIdx.y * 32 + threadIdx.x;
    const int y2 = blockIdx.x * 32 + threadIdx.y;
    #pragma unroll
    for (int i = 0; i < 32; i += 8) {
        float w6 = t[threadIdx.x][threadIdx.y + i] * 64.f;
        __half h = __float2half_rn(w6);
        __half l = __float2half_rn(w6 - __half2float(h));
        dh[(size_t)(y2 + i) * DIM + x2] = h;
        dl[(size_t)(y2 + i) * DIM + x2] = l;
    }
}

// =====================================================================
// GEMM via mma.sync fp16 split-precision, single fp32 accumulator.
// Pass-major MMA scheduling: acc RAW distance = 16 independent MMAs.
// MODE 0: gating, 3 passes (ah*bh, ah*bl, al*bh) -> logits = x@Wg + bg
// MODE 1: expert, 2 passes (ah*bh, ah*bl)        -> out = relu(x@We+be)*p
// 512 threads = 16 warps as 4(m) x 4(n); warp tile 32x64; block 128x256.
// =====================================================================
template <int MODE>
__global__ __launch_bounds__(512, 1) void k_gemm(const float* __restrict__ bias_,
                                                 float* __restrict__ C) {
    extern __shared__ char smem[];
    __shared__ int stok[BM];

    const int tid = threadIdx.x;
    const int lane = tid & 31;
    const int w = tid >> 5;
    const int mbase = blockIdx.y * BM;
    const int nbase = blockIdx.x * BN;

    int e = 0;
    const float* bias = bias_;
    size_t woff = 0;
    if (MODE == 1) {
        e = blockIdx.z;
        const int cnt = g_cnt[e];
        if (mbase >= cnt) return;
        woff = (size_t)(1 + e) * DIM * DIM;
        bias = bias_ + e * DIM;
        if (tid < BM) {
            const int i = mbase + tid;
            stok[tid] = (i < cnt) ? g_tok[e * NTOK + i] : -1;
        }
    } else {
        if (tid < BM) stok[tid] = mbase + tid;
    }
    __syncthreads();

    const uint32_t sb = smem_u32(smem);

    // ---- cp.async jobs: up to 2 rows per thread
    // tid<128:         job0 = Ah row tid,       job1 = Bl row tid
    // tid in 128..255: job0 = Al row tid-128,   job1 = Bl row tid   (job0 skipped MODE 1)
    // tid in 256..511: job0 = Bh row tid-256
    const __half* gp0;
    const __half* gp1 = nullptr;
    uint32_t sz0 = 16u, sz1 = 16u;
    uint32_t so0, so1 = 0;
    bool skip0 = false;
    if (tid < 256) {
        const int r = tid & 127;
        const int tok = stok[r];
        sz0 = (tok >= 0) ? 16u : 0u;
        const __half* base = (tid < 128) ? g_Xh : g_Xl;
        gp0 = base + (size_t)(tok >= 0 ? tok : 0) * DIM;
        so0 = ((tid < 128) ? OFF_AH : OFF_AL) + r * ROWB;
        gp1 = g_Wl + woff + (size_t)(nbase + tid) * DIM;
        so1 = OFF_BL + tid * ROWB;
        if (MODE == 1 && tid >= 128) skip0 = true;  // no Al needed for 2-pass
    } else {
        const int r = tid - 256;
        gp0 = g_Wh + woff + (size_t)(nbase + r) * DIM;
        so0 = OFF_BH + r * ROWB;
    }

    // ---- warp tiling: 16 warps as 4(m) x 4(n); warp tile 32x64
    const int wm = (w & 3) * 32;
    const int wn = (w >> 2) * 64;
    const int lr = lane & 15;
    const int lkb = (lane >> 4) * 16;   // k-half byte offset for ldmatrix

    float acc[2][8][4];
    #pragma unroll
    for (int mi = 0; mi < 2; ++mi)
        #pragma unroll
        for (int nj = 0; nj < 8; ++nj)
            #pragma unroll
            for (int q = 0; q < 4; ++q) acc[mi][nj][q] = 0.f;

    // prologue: stages 0 and 1
    #pragma unroll
    for (int s = 0; s < 2; ++s) {
        const uint32_t d = sb + s * STGB;
        if (!skip0) {
            #pragma unroll
            for (int q = 0; q < 4; ++q)
                CP_ASYNC16(d + so0 + q * 16, (const char*)(gp0 + s * BK) + q * 16, sz0);
        }
        if (tid < 256) {
            #pragma unroll
            for (int q = 0; q < 4; ++q)
                CP_ASYNC16(d + so1 + q * 16, (const char*)(gp1 + s * BK) + q * 16, sz1);
        }
        CP_COMMIT();
    }

    int rd = 0, wr = 2;   // rotating slot indices (mod 3)
    for (int it = 0; it < KIT; ++it) {
        CP_WAIT_1();            // stage `it` complete (stage it+1 may be in flight)
        __syncthreads();        // all warps done reading slot `wr`

        if (it + 2 < KIT) {     // issue loads for stage it+2 into slot wr
            const uint32_t d = sb + wr * STGB;
            const int k0 = (it + 2) * BK;
            if (!skip0) {
                #pragma unroll
                for (int q = 0; q < 4; ++q)
                    CP_ASYNC16(d + so0 + q * 16, (const char*)(gp0 + k0) + q * 16, sz0);
            }
            if (tid < 256) {
                #pragma unroll
                for (int q = 0; q < 4; ++q)
                    CP_ASYNC16(d + so1 + q * 16, (const char*)(gp1 + k0) + q * 16, sz1);
            }
        }
        CP_COMMIT();            // uniform group accounting

        const uint32_t sgb = sb + rd * STGB;
        #pragma unroll
        for (int kk = 0; kk < 2; ++kk) {       // two k16 steps in BK=32
            const uint32_t kb = kk * 32 + lkb;
            uint32_t ah[2][4];
            #pragma unroll
            for (int mi = 0; mi < 2; ++mi) {
                const uint32_t ro = (uint32_t)(wm + mi * 16 + lr) * ROWB + kb;
                LDM_X4(ah[mi], sgb + OFF_AH + ro);
            }
            // ---- pass 1: ah * bh (16 independent MMAs) ----
            #pragma unroll
            for (int njp = 0; njp < 4; ++njp) {
                uint32_t bh[4];
                const uint32_t ro = (uint32_t)(wn + njp * 16 + lr) * ROWB + kb;
                LDM_X4(bh, sgb + OFF_BH + ro);
                #pragma unroll
                for (int mi = 0; mi < 2; ++mi)
                    #pragma unroll
                    for (int t = 0; t < 2; ++t)
                        MMA(acc[mi][njp * 2 + t], ah[mi], bh[t], bh[t + 2]);
            }
            // ---- pass 2: ah * bl (distance 16 from pass 1) ----
            #pragma unroll
            for (int njp = 0; njp < 4; ++njp) {
                uint32_t bl[4];
                const uint32_t ro = (uint32_t)(wn + njp * 16 + lr) * ROWB + kb;
                LDM_X4(bl, sgb + OFF_BL + ro);
                #pragma unroll
                for (int mi = 0; mi < 2; ++mi)
                    #pragma unroll
                    for (int t = 0; t < 2; ++t)
                        MMA(acc[mi][njp * 2 + t], ah[mi], bl[t], bl[t + 2]);
            }
            // ---- pass 3 (gating only): al * bh, bh reloaded ----
            if (MODE == 0) {
                uint32_t al[2][4];
                #pragma unroll
                for (int mi = 0; mi < 2; ++mi) {
                    const uint32_t ro = (uint32_t)(wm + mi * 16 + lr) * ROWB + kb;
                    LDM_X4(al[mi], sgb + OFF_AL + ro);
                }
                #pragma unroll
                for (int njp = 0; njp < 4; ++njp) {
                    uint32_t bh[4];
                    const uint32_t ro = (uint32_t)(wn + njp * 16 + lr) * ROWB + kb;
                    LDM_X4(bh, sgb + OFF_BH + ro);
                    #pragma unroll
                    for (int mi = 0; mi < 2; ++mi)
                        #pragma unroll
                        for (int t = 0; t < 2; ++t)
                            MMA(acc[mi][njp * 2 + t], al[mi], bh[t], bh[t + 2]);
                }
            }
        }
        rd = (rd == 2) ? 0 : rd + 1;
        wr = (wr == 2) ? 0 : wr + 1;
    }

    // ---- epilogue: result is 64*(x@W); scale by 1/64, add bias ----
    const int gid = lane >> 2;
    const int tq = lane & 3;
    #pragma unroll
    for (int mi = 0; mi < 2; ++mi) {
        #pragma unroll
        for (int rh = 0; rh < 2; ++rh) {
            const int mloc = wm + mi * 16 + gid + rh * 8;
            const int tok = stok[mloc];
            if (MODE == 1 && tok < 0) continue;
            const float pt = (MODE == 1) ? g_p[tok] : 1.f;
            float* dst = C + (size_t)tok * DIM;
            #pragma unroll
            for (int nj = 0; nj < 8; ++nj) {
                const int n = nbase + wn + nj * 8 + tq * 2;
                float v0 = acc[mi][nj][rh * 2]     * (1.f / 64.f) + bias[n];
                float v1 = acc[mi][nj][rh * 2 + 1] * (1.f / 64.f) + bias[n + 1];
                if (MODE == 1) {
                    v0 = fmaxf(v0, 0.f) * pt;
                    v1 = fmaxf(v1, 0.f) * pt;
                }
                *(float2*)(dst + n) = make_float2(v0, v1);
            }
        }
    }
}

// =====================================================================
// Routing: 1 block per token; argmax (first-index tie-break) + 1/sum(exp)
// =====================================================================
__global__ __launch_bounds__(256) void k_route() {
    const int t = blockIdx.x;
    const int tid = threadIdx.x;
    const float* row = g_logits + (size_t)t * DIM;

    float4 v = ((const float4*)row)[tid];

    float m = v.x; int mi = tid * 4;
    if (v.y > m) { m = v.y; mi = tid * 4 + 1; }
    if (v.z > m) { m = v.z; mi = tid * 4 + 2; }
    if (v.w > m) { m = v.w; mi = tid * 4 + 3; }

    #pragma unroll
    for (int off = 16; off > 0; off >>= 1) {
        float om = __shfl_down_sync(0xffffffffu, m, off);
        int   oi = __shfl_down_sync(0xffffffffu, mi, off);
        if (om > m || (om == m && oi < mi)) { m = om; mi = oi; }
    }

    __shared__ float sm[8];
    __shared__ int   si[8];
    __shared__ float smax;
    __shared__ int   sarg;

    const int wid = tid >> 5, lane = tid & 31;
    if (lane == 0) { sm[wid] = m; si[wid] = mi; }
    __syncthreads();
    if (tid == 0) {
        float bm_ = sm[0]; int bi = si[0];
        #pragma unroll
        for (int w = 1; w < 8; w++)
            if (sm[w] > bm_ || (sm[w] == bm_ && si[w] < bi)) { bm_ = sm[w]; bi = si[w]; }
        smax = bm_; sarg = bi;
    }
    __syncthreads();

    const float mx = smax;
    float s = expf(v.x - mx) + expf(v.y - mx) + expf(v.z - mx) + expf(v.w - mx);
    #pragma unroll
    for (int off = 16; off > 0; off >>= 1)
        s += __shfl_down_sync(0xffffffffu, s, off);
    if (lane == 0) sm[wid] = s;
    __syncthreads();
    if (tid == 0) {
        float tot = 0.f;
        #pragma unroll
        for (int w = 0; w < 8; w++) tot += sm[w];
        const int ex = sarg & (NEXP - 1);
        const int pos = atomicAdd(&g_cnt[ex], 1);
        g_tok[ex * NTOK + pos] = t;
        g_p[t] = 1.f / tot;
    }
}

// =====================================================================
extern "C" void kernel_launch(void* const* d_in, const int* in_sizes, int n_in,
                              void* d_out, int out_size) {
    const float* x  = (const float*)d_in[0];
    const float* Wg = (const float*)d_in[1];
    const float* bg = (const float*)d_in[2];
    const float* We = (const float*)d_in[3];
    const float* be = (const float*)d_in[4];
    float* out = (float*)d_out;

    float* logits;
    cudaGetSymbolAddress((void**)&logits, g_logits);

    cudaFuncSetAttribute(k_gemm<0>, cudaFuncAttributeMaxDynamicSharedMemorySize, SMEM_BYTES);
    cudaFuncSetAttribute(k_gemm<1>, cudaFuncAttributeMaxDynamicSharedMemorySize, SMEM_BYTES);

    k_init<<<1, 32>>>();
    k_split_x<<<(NTOK * DIM / 4) / 256, 256>>>(x);
    k_split_w<<<dim3(32, 32, 1 + NEXP), dim3(32, 8)>>>(Wg, We);
    k_gemm<0><<<dim3(DIM / BN, NTOK / BM), 512, SMEM_BYTES>>>(bg, logits);
    k_route<<<NTOK, 256>>>();
    k_gemm<1><<<dim3(DIM / BN, NTOK / BM, NEXP), 512, SMEM_BYTES>>>(be, out);
}

// round 9
// speedup vs baseline: 1.3134x; 1.1601x over previous
#include <cuda_runtime.h>
#include <cuda_fp16.h>
#include <math.h>
#include <stdint.h>

#define DIM  1024
#define NEXP 8
#define NTOK 16384
#define BM   128
#define BN   256
#define BK   32
#define KIT  (DIM/BK)        // 32 stages
#define ROWB 80              // bytes per smem row (32 halves data + 16 pad)
// stage layout: Ah(128) | Bh(256) | Bl(256) rows
#define OFF_AH 0
#define OFF_BH (128*ROWB)
#define OFF_BL (OFF_BH + 256*ROWB)
#define STGB   (OFF_BL + 256*ROWB)   // 51200
#define NSTG 3
#define SMEM_BYTES (NSTG*STGB)       // 153600
#define GAP_THRESH 1.0e-2f

// ---------------- device-global scratch (allocation-free) ----------------
__device__ __half g_Xh[(size_t)NTOK * DIM];
__device__ __half g_Wh[(size_t)(1 + NEXP) * DIM * DIM];   // [N][K], W*64
__device__ __half g_Wl[(size_t)(1 + NEXP) * DIM * DIM];   // residual of W*64
__device__ float  g_logits[(size_t)NTOK * DIM];
__device__ int    g_cnt[NEXP];
__device__ int    g_tok[NEXP * NTOK];
__device__ float  g_p[NTOK];

// ---------------- PTX helpers ----------------
static __device__ __forceinline__ uint32_t smem_u32(const void* p) {
    uint32_t a;
    asm("{ .reg .u64 t; cvta.to.shared.u64 t, %1; cvt.u32.u64 %0, t; }" : "=r"(a) : "l"(p));
    return a;
}
#define CP_ASYNC16(dst, src, sz) \
    asm volatile("cp.async.cg.shared.global [%0], [%1], 16, %2;" \
                 :: "r"(dst), "l"(src), "r"(sz) : "memory")
#define CP_COMMIT() asm volatile("cp.async.commit_group;" ::: "memory")
#define CP_WAIT_1() asm volatile("cp.async.wait_group 1;" ::: "memory")

#define LDM_X4(r, addr) \
    asm volatile("ldmatrix.sync.aligned.m8n8.x4.shared.b16 {%0,%1,%2,%3}, [%4];" \
                 : "=r"((r)[0]), "=r"((r)[1]), "=r"((r)[2]), "=r"((r)[3]) : "r"(addr))

#define MMA(d, a, b0_, b1_) \
    asm volatile("mma.sync.aligned.m16n8k16.row.col.f32.f16.f16.f32 " \
                 "{%0,%1,%2,%3},{%4,%5,%6,%7},{%8,%9},{%0,%1,%2,%3};" \
                 : "+f"((d)[0]), "+f"((d)[1]), "+f"((d)[2]), "+f"((d)[3]) \
                 : "r"((a)[0]), "r"((a)[1]), "r"((a)[2]), "r"((a)[3]), \
                   "r"(b0_), "r"(b1_))

// =====================================================================
__global__ void k_init() {
    if (threadIdx.x < NEXP) g_cnt[threadIdx.x] = 0;
}

// x -> fp16 high part only (residual not needed: W carries the split).
__global__ __launch_bounds__(256) void k_split_x(const float* __restrict__ X) {
    const size_t i = (size_t)blockIdx.x * 256 + threadIdx.x;   // float4 index
    float4 v = ((const float4*)X)[i];
    __half h0 = __float2half_rn(v.x), h1 = __float2half_rn(v.y);
    __half h2 = __float2half_rn(v.z), h3 = __float2half_rn(v.w);
    ((__half2*)g_Xh)[2 * i]     = __halves2half2(h0, h1);
    ((__half2*)g_Xh)[2 * i + 1] = __halves2half2(h2, h3);
}

// Transpose W ([K][N] -> [N][K]), scale x64, split to fp16 (h, residual).
__global__ __launch_bounds__(256) void k_split_w(const float* __restrict__ Wg,
                                                 const float* __restrict__ We) {
    __shared__ float t[32][33];
    const int z = blockIdx.z;
    const float* src = (z == 0) ? Wg : (We + (size_t)(z - 1) * DIM * DIM);
    __half* dh = g_Wh + (size_t)z * DIM * DIM;
    __half* dl = g_Wl + (size_t)z * DIM * DIM;
    const int x = blockIdx.x * 32 + threadIdx.x;
    const int y0 = blockIdx.y * 32 + threadIdx.y;
    #pragma unroll
    for (int i = 0; i < 32; i += 8)
        t[threadIdx.y + i][threadIdx.x] = src[(size_t)(y0 + i) * DIM + x];
    __syncthreads();
    const int x2 = blockIdx.y * 32 + threadIdx.x;
    const int y2 = blockIdx.x * 32 + threadIdx.y;
    #pragma unroll
    for (int i = 0; i < 32; i += 8) {
        float w6 = t[threadIdx.x][threadIdx.y + i] * 64.f;
        __half h = __float2half_rn(w6);
        __half l = __float2half_rn(w6 - __half2float(h));
        dh[(size_t)(y2 + i) * DIM + x2] = h;
        dl[(size_t)(y2 + i) * DIM + x2] = l;
    }
}

// =====================================================================
// GEMM via mma.sync, 2-pass split precision: C = A_h * (B_h + B_l).
// 512 threads = 16 warps as 4(m) x 4(n); warp tile 32x64; block 128x256.
// 3-stage cp.async pipeline, one __syncthreads per stage.
// MODE 0: gating  -> logits = x@Wg + bg  (argmax rescued later in k_route)
// MODE 1: expert  -> out = relu(x@We[e] + be[e]) * p   (rows gathered)
// =====================================================================
template <int MODE>
__global__ __launch_bounds__(512, 1) void k_gemm(const float* __restrict__ bias_,
                                                 float* __restrict__ C) {
    extern __shared__ char smem[];
    __shared__ int stok[BM];

    const int tid = threadIdx.x;
    const int lane = tid & 31;
    const int w = tid >> 5;
    const int mbase = blockIdx.y * BM;
    const int nbase = blockIdx.x * BN;

    int e = 0;
    const float* bias = bias_;
    size_t woff = 0;
    if (MODE == 1) {
        e = blockIdx.z;
        const int cnt = g_cnt[e];
        if (mbase >= cnt) return;
        woff = (size_t)(1 + e) * DIM * DIM;
        bias = bias_ + e * DIM;
        if (tid < BM) {
            const int i = mbase + tid;
            stok[tid] = (i < cnt) ? g_tok[e * NTOK + i] : -1;
        }
    } else {
        if (tid < BM) stok[tid] = mbase + tid;
    }
    __syncthreads();

    const uint32_t sb = smem_u32(smem);

    // ---- cp.async jobs (640 rows/stage over 512 threads):
    // job0: tid<128 -> Ah row tid; tid in [128,384) -> Bh row tid-128;
    //       tid in [384,512) -> Bl row tid-384
    // job1 (tid<128 only): Bl row 128+tid
    const __half* gp0;
    const __half* gp1 = nullptr;
    uint32_t sz0 = 16u;
    uint32_t so0, so1 = 0;
    if (tid < 128) {
        const int tok = stok[tid];
        sz0 = (tok >= 0) ? 16u : 0u;
        gp0 = g_Xh + (size_t)(tok >= 0 ? tok : 0) * DIM;
        so0 = OFF_AH + tid * ROWB;
        gp1 = g_Wl + woff + (size_t)(nbase + 128 + tid) * DIM;
        so1 = OFF_BL + (128 + tid) * ROWB;
    } else if (tid < 384) {
        const int r = tid - 128;
        gp0 = g_Wh + woff + (size_t)(nbase + r) * DIM;
        so0 = OFF_BH + r * ROWB;
    } else {
        const int r = tid - 384;
        gp0 = g_Wl + woff + (size_t)(nbase + r) * DIM;
        so0 = OFF_BL + r * ROWB;
    }

    // ---- warp tiling: 16 warps as 4(m) x 4(n); warp tile 32x64
    const int wm = (w & 3) * 32;
    const int wn = (w >> 2) * 64;
    const int lr = lane & 15;
    const int lkb = (lane >> 4) * 16;   // k-half byte offset for ldmatrix

    float acc[2][8][4];
    #pragma unroll
    for (int mi = 0; mi < 2; ++mi)
        #pragma unroll
        for (int nj = 0; nj < 8; ++nj)
            #pragma unroll
            for (int q = 0; q < 4; ++q) acc[mi][nj][q] = 0.f;

    // prologue: stages 0 and 1
    #pragma unroll
    for (int s = 0; s < 2; ++s) {
        const uint32_t d = sb + s * STGB;
        #pragma unroll
        for (int q = 0; q < 4; ++q)
            CP_ASYNC16(d + so0 + q * 16, (const char*)(gp0 + s * BK) + q * 16, sz0);
        if (tid < 128) {
            #pragma unroll
            for (int q = 0; q < 4; ++q)
                CP_ASYNC16(d + so1 + q * 16, (const char*)(gp1 + s * BK) + q * 16, 16u);
        }
        CP_COMMIT();
    }

    int rd = 0, wr = 2;   // rotating slot indices (mod 3)
    for (int it = 0; it < KIT; ++it) {
        CP_WAIT_1();            // stage `it` complete (stage it+1 may be in flight)
        __syncthreads();        // all warps done reading slot `wr`

        if (it + 2 < KIT) {     // issue loads for stage it+2 into slot wr
            const uint32_t d = sb + wr * STGB;
            const int k0 = (it + 2) * BK;
            #pragma unroll
            for (int q = 0; q < 4; ++q)
                CP_ASYNC16(d + so0 + q * 16, (const char*)(gp0 + k0) + q * 16, sz0);
            if (tid < 128) {
                #pragma unroll
                for (int q = 0; q < 4; ++q)
                    CP_ASYNC16(d + so1 + q * 16, (const char*)(gp1 + k0) + q * 16, 16u);
            }
        }
        CP_COMMIT();            // uniform group accounting

        const uint32_t sgb = sb + rd * STGB;
        #pragma unroll
        for (int kk = 0; kk < 2; ++kk) {       // two k16 steps in BK=32
            const uint32_t kb = kk * 32 + lkb;
            uint32_t ah[2][4];
            #pragma unroll
            for (int mi = 0; mi < 2; ++mi) {
                const uint32_t ro = (uint32_t)(wm + mi * 16 + lr) * ROWB + kb;
                LDM_X4(ah[mi], sgb + OFF_AH + ro);
            }
            // ---- pass 1: ah * bh (16 independent MMAs) ----
            #pragma unroll
            for (int njp = 0; njp < 4; ++njp) {
                uint32_t bh[4];
                const uint32_t ro = (uint32_t)(wn + njp * 16 + lr) * ROWB + kb;
                LDM_X4(bh, sgb + OFF_BH + ro);
                #pragma unroll
                for (int mi = 0; mi < 2; ++mi)
                    #pragma unroll
                    for (int t = 0; t < 2; ++t)
                        MMA(acc[mi][njp * 2 + t], ah[mi], bh[t], bh[t + 2]);
            }
            // ---- pass 2: ah * bl ----
            #pragma unroll
            for (int njp = 0; njp < 4; ++njp) {
                uint32_t bl[4];
                const uint32_t ro = (uint32_t)(wn + njp * 16 + lr) * ROWB + kb;
                LDM_X4(bl, sgb + OFF_BL + ro);
                #pragma unroll
                for (int mi = 0; mi < 2; ++mi)
                    #pragma unroll
                    for (int t = 0; t < 2; ++t)
                        MMA(acc[mi][njp * 2 + t], ah[mi], bl[t], bl[t + 2]);
            }
        }
        rd = (rd == 2) ? 0 : rd + 1;
        wr = (wr == 2) ? 0 : wr + 1;
    }

    // ---- epilogue: result is 64*(x@W); scale by 1/64, add bias ----
    const int gid = lane >> 2;
    const int tq = lane & 3;
    #pragma unroll
    for (int mi = 0; mi < 2; ++mi) {
        #pragma unroll
        for (int rh = 0; rh < 2; ++rh) {
            const int mloc = wm + mi * 16 + gid + rh * 8;
            const int tok = stok[mloc];
            if (MODE == 1 && tok < 0) continue;
            const float pt = (MODE == 1) ? g_p[tok] : 1.f;
            float* dst = C + (size_t)tok * DIM;
            #pragma unroll
            for (int nj = 0; nj < 8; ++nj) {
                const int n = nbase + wn + nj * 8 + tq * 2;
                float v0 = acc[mi][nj][rh * 2]     * (1.f / 64.f) + bias[n];
                float v1 = acc[mi][nj][rh * 2 + 1] * (1.f / 64.f) + bias[n + 1];
                if (MODE == 1) {
                    v0 = fmaxf(v0, 0.f) * pt;
                    v1 = fmaxf(v1, 0.f) * pt;
                }
                *(float2*)(dst + n) = make_float2(v0, v1);
            }
        }
    }
}

// =====================================================================
// Routing with top-2 tracking + exact fp32 rescue of ambiguous argmax.
// 1 block (256 thr) per token.
// =====================================================================
static __device__ __forceinline__ void merge_top2(float& m1, int& i1, float& m2, int& i2,
                                                  float om1, int oi1, float om2, int oi2) {
    if (om1 > m1 || (om1 == m1 && oi1 < i1)) {
        float c = m1; int ci = i1;
        m1 = om1; i1 = oi1;
        if (om2 > c || (om2 == c && oi2 < ci)) { m2 = om2; i2 = oi2; }
        else                                   { m2 = c;   i2 = ci;  }
    } else {
        if (om1 > m2 || (om1 == m2 && oi1 < i2)) { m2 = om1; i2 = oi1; }
    }
}

__global__ __launch_bounds__(256) void k_route(const float* __restrict__ X,
                                               const float* __restrict__ Wg,
                                               const float* __restrict__ bg) {
    const int t = blockIdx.x;
    const int tid = threadIdx.x;
    const float* row = g_logits + (size_t)t * DIM;

    float4 v = ((const float4*)row)[tid];

    // per-thread top-2 over 4 values
    float m1 = v.x; int i1 = tid * 4;
    float m2 = -3.4e38f; int i2 = 0x7fffffff;
    {
        float vals[3] = {v.y, v.z, v.w};
        #pragma unroll
        for (int j = 0; j < 3; ++j) {
            const int idx = tid * 4 + 1 + j;
            const float val = vals[j];
            if (val > m1) { m2 = m1; i2 = i1; m1 = val; i1 = idx; }
            else if (val > m2) { m2 = val; i2 = idx; }
        }
    }
    // warp merge
    #pragma unroll
    for (int off = 16; off > 0; off >>= 1) {
        float om1 = __shfl_down_sync(0xffffffffu, m1, off);
        int   oi1 = __shfl_down_sync(0xffffffffu, i1, off);
        float om2 = __shfl_down_sync(0xffffffffu, m2, off);
        int   oi2 = __shfl_down_sync(0xffffffffu, i2, off);
        merge_top2(m1, i1, m2, i2, om1, oi1, om2, oi2);
    }

    __shared__ float sm1[8], sm2[8];
    __shared__ int   si1[8], si2[8];
    __shared__ float s_top1, s_top2;
    __shared__ int   s_i1, s_i2;
    __shared__ float s_sum;
    __shared__ float red[16];

    const int wid = tid >> 5, lane = tid & 31;
    if (lane == 0) { sm1[wid] = m1; si1[wid] = i1; sm2[wid] = m2; si2[wid] = i2; }
    __syncthreads();
    if (tid == 0) {
        float b1 = sm1[0], b2 = sm2[0]; int bi1 = si1[0], bi2 = si2[0];
        #pragma unroll
        for (int w = 1; w < 8; w++)
            merge_top2(b1, bi1, b2, bi2, sm1[w], si1[w], sm2[w], si2[w]);
        s_top1 = b1; s_i1 = bi1; s_top2 = b2; s_i2 = bi2;
    }
    __syncthreads();

    const float mx = s_top1;
    // softmax denominator
    float s = expf(v.x - mx) + expf(v.y - mx) + expf(v.z - mx) + expf(v.w - mx);
    #pragma unroll
    for (int off = 16; off > 0; off >>= 1)
        s += __shfl_down_sync(0xffffffffu, s, off);
    if (lane == 0) sm1[wid] = s;
    __syncthreads();
    if (tid == 0) {
        float tot = 0.f;
        #pragma unroll
        for (int w = 0; w < 8; w++) tot += sm1[w];
        s_sum = tot;
    }
    __syncthreads();

    int   chosen = s_i1;
    float l_ch   = s_top1;
    const bool ambiguous = (s_top1 - s_top2) < GAP_THRESH;
    if (ambiguous) {
        // exact fp32 recompute of the two candidate logits
        const int c1 = s_i1, c2 = s_i2;
        float p1 = 0.f, p2 = 0.f;
        const float* xr = X + (size_t)t * DIM;
        for (int k = tid; k < DIM; k += 256) {
            const float xv = xr[k];
            p1 += xv * Wg[(size_t)k * DIM + c1];
            p2 += xv * Wg[(size_t)k * DIM + c2];
        }
        #pragma unroll
        for (int off = 16; off > 0; off >>= 1) {
            p1 += __shfl_down_sync(0xffffffffu, p1, off);
            p2 += __shfl_down_sync(0xffffffffu, p2, off);
        }
        if (lane == 0) { red[wid] = p1; red[8 + wid] = p2; }
        __syncthreads();
        if (tid == 0) {
            float d1 = bg[c1], d2 = bg[c2];
            #pragma unroll
            for (int w = 0; w < 8; w++) { d1 += red[w]; d2 += red[8 + w]; }
            if (d2 > d1 || (d2 == d1 && c2 < c1)) { s_i1 = c2; s_top1 = s_top2; }
        }
        __syncthreads();
        chosen = s_i1;
        l_ch = s_top1;   // approx logit of chosen (for p)
    }

    if (tid == 0) {
        const int ex = chosen & (NEXP - 1);
        const int pos = atomicAdd(&g_cnt[ex], 1);
        g_tok[ex * NTOK + pos] = t;
        g_p[t] = expf(l_ch - mx) / s_sum;
    }
}

// =====================================================================
extern "C" void kernel_launch(void* const* d_in, const int* in_sizes, int n_in,
                              void* d_out, int out_size) {
    const float* x  = (const float*)d_in[0];
    const float* Wg = (const float*)d_in[1];
    const float* bg = (const float*)d_in[2];
    const float* We = (const float*)d_in[3];
    const float* be = (const float*)d_in[4];
    float* out = (float*)d_out;

    float* logits;
    cudaGetSymbolAddress((void**)&logits, g_logits);

    cudaFuncSetAttribute(k_gemm<0>, cudaFuncAttributeMaxDynamicSharedMemorySize, SMEM_BYTES);
    cudaFuncSetAttribute(k_gemm<1>, cudaFuncAttributeMaxDynamicSharedMemorySize, SMEM_BYTES);

    k_init<<<1, 32>>>();
    k_split_x<<<(NTOK * DIM / 4) / 256, 256>>>(x);
    k_split_w<<<dim3(32, 32, 1 + NEXP), dim3(32, 8)>>>(Wg, We);
    k_gemm<0><<<dim3(DIM / BN, NTOK / BM), 512, SMEM_BYTES>>>(bg, logits);
    k_route<<<NTOK, 256>>>(x, Wg, bg);
    k_gemm<1><<<dim3(DIM / BN, NTOK / BM, NEXP), 512, SMEM_BYTES>>>(be, out);
}

// round 10
// speedup vs baseline: 2.1729x; 1.6544x over previous
#include <cuda_runtime.h>
#include <cuda_fp16.h>
#include <math.h>
#include <stdint.h>

#define DIM  1024
#define NEXP 8
#define NTOK 16384
#define BM   128
#define BN   256
#define BK   32
#define KIT  (DIM/BK)        // 32 stages
#define ROWB 80              // bytes per smem row (32 halves data + 16 pad)
// stage layout: Ah(128) | Bh(256) rows
#define OFF_AH 0
#define OFF_BH (128*ROWB)
#define STGB   (OFF_BH + 256*ROWB)   // 30720
#define NSTG 3
#define SMEM_BYTES (NSTG*STGB)       // 92160
#define GAP_THRESH 5.0e-3f

// ---------------- device-global scratch (allocation-free) ----------------
__device__ __half g_Xh[(size_t)NTOK * DIM];
__device__ __half g_Wh[(size_t)(1 + NEXP) * DIM * DIM];   // [N][K] fp16
__device__ float  g_logits[(size_t)NTOK * DIM];
__device__ int    g_cnt[NEXP];
__device__ int    g_tok[NEXP * NTOK];
__device__ float  g_p[NTOK];

// ---------------- PTX helpers ----------------
static __device__ __forceinline__ uint32_t smem_u32(const void* p) {
    uint32_t a;
    asm("{ .reg .u64 t; cvta.to.shared.u64 t, %1; cvt.u32.u64 %0, t; }" : "=r"(a) : "l"(p));
    return a;
}
#define CP_ASYNC16(dst, src, sz) \
    asm volatile("cp.async.cg.shared.global [%0], [%1], 16, %2;" \
                 :: "r"(dst), "l"(src), "r"(sz) : "memory")
#define CP_COMMIT() asm volatile("cp.async.commit_group;" ::: "memory")
#define CP_WAIT_1() asm volatile("cp.async.wait_group 1;" ::: "memory")

#define LDM_X4(r, addr) \
    asm volatile("ldmatrix.sync.aligned.m8n8.x4.shared.b16 {%0,%1,%2,%3}, [%4];" \
                 : "=r"((r)[0]), "=r"((r)[1]), "=r"((r)[2]), "=r"((r)[3]) : "r"(addr))

#define MMA(d, a, b0_, b1_) \
    asm volatile("mma.sync.aligned.m16n8k16.row.col.f32.f16.f16.f32 " \
                 "{%0,%1,%2,%3},{%4,%5,%6,%7},{%8,%9},{%0,%1,%2,%3};" \
                 : "+f"((d)[0]), "+f"((d)[1]), "+f"((d)[2]), "+f"((d)[3]) \
                 : "r"((a)[0]), "r"((a)[1]), "r"((a)[2]), "r"((a)[3]), \
                   "r"(b0_), "r"(b1_))

// =====================================================================
__global__ void k_init() {
    if (threadIdx.x < NEXP) g_cnt[threadIdx.x] = 0;
}

// x -> fp16 (round-to-nearest)
__global__ __launch_bounds__(256) void k_split_x(const float* __restrict__ X) {
    const size_t i = (size_t)blockIdx.x * 256 + threadIdx.x;   // float4 index
    float4 v = ((const float4*)X)[i];
    ((__half2*)g_Xh)[2 * i]     = __halves2half2(__float2half_rn(v.x), __float2half_rn(v.y));
    ((__half2*)g_Xh)[2 * i + 1] = __halves2half2(__float2half_rn(v.z), __float2half_rn(v.w));
}

// Transpose W ([K][N] -> [N][K]) and convert to fp16.
__global__ __launch_bounds__(256) void k_split_w(const float* __restrict__ Wg,
                                                 const float* __restrict__ We) {
    __shared__ float t[32][33];
    const int z = blockIdx.z;
    const float* src = (z == 0) ? Wg : (We + (size_t)(z - 1) * DIM * DIM);
    __half* dh = g_Wh + (size_t)z * DIM * DIM;
    const int x = blockIdx.x * 32 + threadIdx.x;
    const int y0 = blockIdx.y * 32 + threadIdx.y;
    #pragma unroll
    for (int i = 0; i < 32; i += 8)
        t[threadIdx.y + i][threadIdx.x] = src[(size_t)(y0 + i) * DIM + x];
    __syncthreads();
    const int x2 = blockIdx.y * 32 + threadIdx.x;
    const int y2 = blockIdx.x * 32 + threadIdx.y;
    #pragma unroll
    for (int i = 0; i < 32; i += 8)
        dh[(size_t)(y2 + i) * DIM + x2] = __float2half_rn(t[threadIdx.x][threadIdx.y + i]);
}

// =====================================================================
// Plain fp16 GEMM via mma.sync (fp32 accumulate), 1 pass.
// 512 threads = 16 warps as 4(m) x 4(n); warp tile 32x64; block 128x256.
// 3-stage cp.async pipeline, one __syncthreads per stage.
// MODE 0: gating  -> logits = x@Wg + bg  (argmax rescued exactly in k_route)
// MODE 1: expert  -> out = relu(x@We[e] + be[e]) * p   (rows gathered)
// =====================================================================
template <int MODE>
__global__ __launch_bounds__(512, 1) void k_gemm(const float* __restrict__ bias_,
                                                 float* __restrict__ C) {
    extern __shared__ char smem[];
    __shared__ int stok[BM];

    const int tid = threadIdx.x;
    const int lane = tid & 31;
    const int w = tid >> 5;
    const int mbase = blockIdx.y * BM;
    const int nbase = blockIdx.x * BN;

    int e = 0;
    const float* bias = bias_;
    size_t woff = 0;
    if (MODE == 1) {
        e = blockIdx.z;
        const int cnt = g_cnt[e];
        if (mbase >= cnt) return;
        woff = (size_t)(1 + e) * DIM * DIM;
        bias = bias_ + e * DIM;
        if (tid < BM) {
            const int i = mbase + tid;
            stok[tid] = (i < cnt) ? g_tok[e * NTOK + i] : -1;
        }
    } else {
        if (tid < BM) stok[tid] = mbase + tid;
    }
    __syncthreads();

    const uint32_t sb = smem_u32(smem);

    // ---- cp.async: 384 rows/stage; tid<128 -> Ah row tid; tid in [128,384) -> Bh
    const __half* gp0 = nullptr;
    uint32_t sz0 = 16u;
    uint32_t so0 = 0;
    const bool has_job = (tid < 384);
    if (tid < 128) {
        const int tok = stok[tid];
        sz0 = (tok >= 0) ? 16u : 0u;
        gp0 = g_Xh + (size_t)(tok >= 0 ? tok : 0) * DIM;
        so0 = OFF_AH + tid * ROWB;
    } else if (tid < 384) {
        const int r = tid - 128;
        gp0 = g_Wh + woff + (size_t)(nbase + r) * DIM;
        so0 = OFF_BH + r * ROWB;
    }

    // ---- warp tiling: 16 warps as 4(m) x 4(n); warp tile 32x64
    const int wm = (w & 3) * 32;
    const int wn = (w >> 2) * 64;
    const int lr = lane & 15;
    const int lkb = (lane >> 4) * 16;   // k-half byte offset for ldmatrix

    float acc[2][8][4];
    #pragma unroll
    for (int mi = 0; mi < 2; ++mi)
        #pragma unroll
        for (int nj = 0; nj < 8; ++nj)
            #pragma unroll
            for (int q = 0; q < 4; ++q) acc[mi][nj][q] = 0.f;

    // prologue: stages 0 and 1
    #pragma unroll
    for (int s = 0; s < 2; ++s) {
        if (has_job) {
            const uint32_t d = sb + s * STGB;
            #pragma unroll
            for (int q = 0; q < 4; ++q)
                CP_ASYNC16(d + so0 + q * 16, (const char*)(gp0 + s * BK) + q * 16, sz0);
        }
        CP_COMMIT();
    }

    int rd = 0, wr = 2;   // rotating slot indices (mod 3)
    for (int it = 0; it < KIT; ++it) {
        CP_WAIT_1();            // stage `it` complete (stage it+1 may be in flight)
        __syncthreads();        // all warps done reading slot `wr`

        if (it + 2 < KIT && has_job) {  // loads for stage it+2 into slot wr
            const uint32_t d = sb + wr * STGB;
            const int k0 = (it + 2) * BK;
            #pragma unroll
            for (int q = 0; q < 4; ++q)
                CP_ASYNC16(d + so0 + q * 16, (const char*)(gp0 + k0) + q * 16, sz0);
        }
        CP_COMMIT();            // uniform group accounting

        const uint32_t sgb = sb + rd * STGB;
        #pragma unroll
        for (int kk = 0; kk < 2; ++kk) {       // two k16 steps in BK=32
            const uint32_t kb = kk * 32 + lkb;
            uint32_t ah[2][4];
            #pragma unroll
            for (int mi = 0; mi < 2; ++mi) {
                const uint32_t ro = (uint32_t)(wm + mi * 16 + lr) * ROWB + kb;
                LDM_X4(ah[mi], sgb + OFF_AH + ro);
            }
            #pragma unroll
            for (int njp = 0; njp < 4; ++njp) {
                uint32_t bh[4];
                const uint32_t ro = (uint32_t)(wn + njp * 16 + lr) * ROWB + kb;
                LDM_X4(bh, sgb + OFF_BH + ro);
                #pragma unroll
                for (int mi = 0; mi < 2; ++mi)
                    #pragma unroll
                    for (int t = 0; t < 2; ++t)
                        MMA(acc[mi][njp * 2 + t], ah[mi], bh[t], bh[t + 2]);
            }
        }
        rd = (rd == 2) ? 0 : rd + 1;
        wr = (wr == 2) ? 0 : wr + 1;
    }

    // ---- epilogue ----
    const int gid = lane >> 2;
    const int tq = lane & 3;
    #pragma unroll
    for (int mi = 0; mi < 2; ++mi) {
        #pragma unroll
        for (int rh = 0; rh < 2; ++rh) {
            const int mloc = wm + mi * 16 + gid + rh * 8;
            const int tok = stok[mloc];
            if (MODE == 1 && tok < 0) continue;
            const float pt = (MODE == 1) ? g_p[tok] : 1.f;
            float* dst = C + (size_t)tok * DIM;
            #pragma unroll
            for (int nj = 0; nj < 8; ++nj) {
                const int n = nbase + wn + nj * 8 + tq * 2;
                float v0 = acc[mi][nj][rh * 2]     + bias[n];
                float v1 = acc[mi][nj][rh * 2 + 1] + bias[n + 1];
                if (MODE == 1) {
                    v0 = fmaxf(v0, 0.f) * pt;
                    v1 = fmaxf(v1, 0.f) * pt;
                }
                *(float2*)(dst + n) = make_float2(v0, v1);
            }
        }
    }
}

// =====================================================================
// Routing with top-2 tracking + exact fp32 rescue of ambiguous argmax.
// 1 block (256 thr) per token.
// =====================================================================
static __device__ __forceinline__ void merge_top2(float& m1, int& i1, float& m2, int& i2,
                                                  float om1, int oi1, float om2, int oi2) {
    if (om1 > m1 || (om1 == m1 && oi1 < i1)) {
        float c = m1; int ci = i1;
        m1 = om1; i1 = oi1;
        if (om2 > c || (om2 == c && oi2 < ci)) { m2 = om2; i2 = oi2; }
        else                                   { m2 = c;   i2 = ci;  }
    } else {
        if (om1 > m2 || (om1 == m2 && oi1 < i2)) { m2 = om1; i2 = oi1; }
    }
}

__global__ __launch_bounds__(256) void k_route(const float* __restrict__ X,
                                               const float* __restrict__ Wg,
                                               const float* __restrict__ bg) {
    const int t = blockIdx.x;
    const int tid = threadIdx.x;
    const float* row = g_logits + (size_t)t * DIM;

    float4 v = ((const float4*)row)[tid];

    // per-thread top-2 over 4 values
    float m1 = v.x; int i1 = tid * 4;
    float m2 = -3.4e38f; int i2 = 0x7fffffff;
    {
        float vals[3] = {v.y, v.z, v.w};
        #pragma unroll
        for (int j = 0; j < 3; ++j) {
            const int idx = tid * 4 + 1 + j;
            const float val = vals[j];
            if (val > m1) { m2 = m1; i2 = i1; m1 = val; i1 = idx; }
            else if (val > m2) { m2 = val; i2 = idx; }
        }
    }
    // warp merge
    #pragma unroll
    for (int off = 16; off > 0; off >>= 1) {
        float om1 = __shfl_down_sync(0xffffffffu, m1, off);
        int   oi1 = __shfl_down_sync(0xffffffffu, i1, off);
        float om2 = __shfl_down_sync(0xffffffffu, m2, off);
        int   oi2 = __shfl_down_sync(0xffffffffu, i2, off);
        merge_top2(m1, i1, m2, i2, om1, oi1, om2, oi2);
    }

    __shared__ float sm1[8], sm2[8];
    __shared__ int   si1[8], si2[8];
    __shared__ float s_top1, s_top2;
    __shared__ int   s_i1, s_i2;
    __shared__ float s_sum;
    __shared__ float red[16];

    const int wid = tid >> 5, lane = tid & 31;
    if (lane == 0) { sm1[wid] = m1; si1[wid] = i1; sm2[wid] = m2; si2[wid] = i2; }
    __syncthreads();
    if (tid == 0) {
        float b1 = sm1[0], b2 = sm2[0]; int bi1 = si1[0], bi2 = si2[0];
        #pragma unroll
        for (int w = 1; w < 8; w++)
            merge_top2(b1, bi1, b2, bi2, sm1[w], si1[w], sm2[w], si2[w]);
        s_top1 = b1; s_i1 = bi1; s_top2 = b2; s_i2 = bi2;
    }
    __syncthreads();

    const float mx = s_top1;
    // softmax denominator
    float s = expf(v.x - mx) + expf(v.y - mx) + expf(v.z - mx) + expf(v.w - mx);
    #pragma unroll
    for (int off = 16; off > 0; off >>= 1)
        s += __shfl_down_sync(0xffffffffu, s, off);
    if (lane == 0) sm1[wid] = s;
    __syncthreads();
    if (tid == 0) {
        float tot = 0.f;
        #pragma unroll
        for (int w = 0; w < 8; w++) tot += sm1[w];
        s_sum = tot;
    }
    __syncthreads();

    int   chosen = s_i1;
    float l_ch   = s_top1;
    const bool ambiguous = (s_top1 - s_top2) < GAP_THRESH;
    if (ambiguous) {
        // exact fp32 recompute of the two candidate logits
        const int c1 = s_i1, c2 = s_i2;
        float p1 = 0.f, p2 = 0.f;
        const float* xr = X + (size_t)t * DIM;
        for (int k = tid; k < DIM; k += 256) {
            const float xv = xr[k];
            p1 += xv * Wg[(size_t)k * DIM + c1];
            p2 += xv * Wg[(size_t)k * DIM + c2];
        }
        #pragma unroll
        for (int off = 16; off > 0; off >>= 1) {
            p1 += __shfl_down_sync(0xffffffffu, p1, off);
            p2 += __shfl_down_sync(0xffffffffu, p2, off);
        }
        if (lane == 0) { red[wid] = p1; red[8 + wid] = p2; }
        __syncthreads();
        if (tid == 0) {
            float d1 = bg[c1], d2 = bg[c2];
            #pragma unroll
            for (int w = 0; w < 8; w++) { d1 += red[w]; d2 += red[8 + w]; }
            if (d2 > d1 || (d2 == d1 && c2 < c1)) { s_i1 = c2; s_top1 = s_top2; }
        }
        __syncthreads();
        chosen = s_i1;
        l_ch = s_top1;   // approx logit of chosen (for p)
    }

    if (tid == 0) {
        const int ex = chosen & (NEXP - 1);
        const int pos = atomicAdd(&g_cnt[ex], 1);
        g_tok[ex * NTOK + pos] = t;
        g_p[t] = expf(l_ch - mx) / s_sum;
    }
}

// =====================================================================
extern "C" void kernel_launch(void* const* d_in, const int* in_sizes, int n_in,
                              void* d_out, int out_size) {
    const float* x  = (const float*)d_in[0];
    const float* Wg = (const float*)d_in[1];
    const float* bg = (const float*)d_in[2];
    const float* We = (const float*)d_in[3];
    const float* be = (const float*)d_in[4];
    float* out = (float*)d_out;

    float* logits;
    cudaGetSymbolAddress((void**)&logits, g_logits);

    cudaFuncSetAttribute(k_gemm<0>, cudaFuncAttributeMaxDynamicSharedMemorySize, SMEM_BYTES);
    cudaFuncSetAttribute(k_gemm<1>, cudaFuncAttributeMaxDynamicSharedMemorySize, SMEM_BYTES);

    k_init<<<1, 32>>>();
    k_split_x<<<(NTOK * DIM / 4) / 256, 256>>>(x);
    k_split_w<<<dim3(32, 32, 1 + NEXP), dim3(32, 8)>>>(Wg, We);
    k_gemm<0><<<dim3(DIM / BN, NTOK / BM), 512, SMEM_BYTES>>>(bg, logits);
    k_route<<<NTOK, 256>>>(x, Wg, bg);
    k_gemm<1><<<dim3(DIM / BN, NTOK / BM, NEXP), 512, SMEM_BYTES>>>(be, out);
}

// round 11
// speedup vs baseline: 2.8216x; 1.2985x over previous
#include <cuda_runtime.h>
#include <cuda_fp16.h>
#include <math.h>
#include <stdint.h>

#define DIM  1024
#define NEXP 8
#define NTOK 16384
#define BM   128
#define BN   256
#define BK   64
#define KIT  (DIM/BK)        // 16 stages
#define ROWB 144             // 64 halves (128B) + 16B pad
// stage layout: Ah(128) | Bh(256) rows
#define OFF_AH 0
#define OFF_BH (128*ROWB)               // 18432
#define STGB   (OFF_BH + 256*ROWB)      // 55296
#define NSTG 3
#define SMEM_BYTES (NSTG*STGB)          // 165888
#define GAP_THRESH 5.0e-3f

// ---------------- device-global scratch (allocation-free) ----------------
__device__ __half g_Xh[(size_t)NTOK * DIM];
__device__ __half g_Wh[(size_t)(1 + NEXP) * DIM * DIM];   // [N][K] fp16
__device__ float  g_part[(size_t)NTOK * 32];              // per token x 4 tiles x 8 words
__device__ int    g_cnt[NEXP];
__device__ int    g_tok[NEXP * NTOK];
__device__ float  g_p[NTOK];

// ---------------- PTX helpers ----------------
static __device__ __forceinline__ uint32_t smem_u32(const void* p) {
    uint32_t a;
    asm("{ .reg .u64 t; cvta.to.shared.u64 t, %1; cvt.u32.u64 %0, t; }" : "=r"(a) : "l"(p));
    return a;
}
#define CP_ASYNC16(dst, src, sz) \
    asm volatile("cp.async.cg.shared.global [%0], [%1], 16, %2;" \
                 :: "r"(dst), "l"(src), "r"(sz) : "memory")
#define CP_COMMIT() asm volatile("cp.async.commit_group;" ::: "memory")
#define CP_WAIT_1() asm volatile("cp.async.wait_group 1;" ::: "memory")

#define LDM_X4(r, addr) \
    asm volatile("ldmatrix.sync.aligned.m8n8.x4.shared.b16 {%0,%1,%2,%3}, [%4];" \
                 : "=r"((r)[0]), "=r"((r)[1]), "=r"((r)[2]), "=r"((r)[3]) : "r"(addr))

#define MMA(d, a, b0_, b1_) \
    asm volatile("mma.sync.aligned.m16n8k16.row.col.f32.f16.f16.f32 " \
                 "{%0,%1,%2,%3},{%4,%5,%6,%7},{%8,%9},{%0,%1,%2,%3};" \
                 : "+f"((d)[0]), "+f"((d)[1]), "+f"((d)[2]), "+f"((d)[3]) \
                 : "r"((a)[0]), "r"((a)[1]), "r"((a)[2]), "r"((a)[3]), \
                   "r"(b0_), "r"(b1_))

// ---- top-2 merge (first-index tie-break, jnp.argmax compatible) ----
static __device__ __forceinline__ void merge_top2(float& m1, int& i1, float& m2, int& i2,
                                                  float om1, int oi1, float om2, int oi2) {
    if (om1 > m1 || (om1 == m1 && oi1 < i1)) {
        float c = m1; int ci = i1;
        m1 = om1; i1 = oi1;
        if (om2 > c || (om2 == c && oi2 < ci)) { m2 = om2; i2 = oi2; }
        else                                   { m2 = c;   i2 = ci;  }
    } else {
        if (om1 > m2 || (om1 == m2 && oi1 < i2)) { m2 = om1; i2 = oi1; }
    }
}
// top-2 + online-softmax-sum merge
static __device__ __forceinline__ void merge5(float& m1, int& i1, float& m2, int& i2, float& s,
                                              float om1, int oi1, float om2, int oi2, float os) {
    const float M = fmaxf(m1, om1);
    s = s * expf(m1 - M) + os * expf(om1 - M);
    merge_top2(m1, i1, m2, i2, om1, oi1, om2, oi2);
}

// =====================================================================
__global__ void k_init() {
    if (threadIdx.x < NEXP) g_cnt[threadIdx.x] = 0;
}

// x -> fp16
__global__ __launch_bounds__(256) void k_split_x(const float* __restrict__ X) {
    const size_t i = (size_t)blockIdx.x * 256 + threadIdx.x;
    float4 v = ((const float4*)X)[i];
    ((__half2*)g_Xh)[2 * i]     = __halves2half2(__float2half_rn(v.x), __float2half_rn(v.y));
    ((__half2*)g_Xh)[2 * i + 1] = __halves2half2(__float2half_rn(v.z), __float2half_rn(v.w));
}

// Transpose W ([K][N] -> [N][K]) and convert to fp16.
__global__ __launch_bounds__(256) void k_split_w(const float* __restrict__ Wg,
                                                 const float* __restrict__ We) {
    __shared__ float t[32][33];
    const int z = blockIdx.z;
    const float* src = (z == 0) ? Wg : (We + (size_t)(z - 1) * DIM * DIM);
    __half* dh = g_Wh + (size_t)z * DIM * DIM;
    const int x = blockIdx.x * 32 + threadIdx.x;
    const int y0 = blockIdx.y * 32 + threadIdx.y;
    #pragma unroll
    for (int i = 0; i < 32; i += 8)
        t[threadIdx.y + i][threadIdx.x] = src[(size_t)(y0 + i) * DIM + x];
    __syncthreads();
    const int x2 = blockIdx.y * 32 + threadIdx.x;
    const int y2 = blockIdx.x * 32 + threadIdx.y;
    #pragma unroll
    for (int i = 0; i < 32; i += 8)
        dh[(size_t)(y2 + i) * DIM + x2] = __float2half_rn(t[threadIdx.x][threadIdx.y + i]);
}

// =====================================================================
// fp16 GEMM via mma.sync (fp32 acc), BK=64, 3-stage cp.async pipeline.
// 512 threads = 16 warps as 4(m) x 4(n); warp tile 32x64; block 128x256.
// MODE 0: gating -> per-token routing partials (top2 + sumexp), no logit store
// MODE 1: expert -> out = relu(x@We[e] + be[e]) * p   (rows gathered)
// =====================================================================
template <int MODE>
__global__ __launch_bounds__(512, 1) void k_gemm(const float* __restrict__ bias_,
                                                 float* __restrict__ C) {
    extern __shared__ char smem[];
    __shared__ int stok[BM];

    const int tid = threadIdx.x;
    const int lane = tid & 31;
    const int w = tid >> 5;
    const int mbase = blockIdx.y * BM;
    const int nbase = blockIdx.x * BN;

    const float* bias = bias_;
    size_t woff = 0;
    if (MODE == 1) {
        const int e = blockIdx.z;
        const int cnt = g_cnt[e];
        if (mbase >= cnt) return;
        woff = (size_t)(1 + e) * DIM * DIM;
        bias = bias_ + e * DIM;
        if (tid < BM) {
            const int i = mbase + tid;
            stok[tid] = (i < cnt) ? g_tok[e * NTOK + i] : -1;
        }
    } else {
        if (tid < BM) stok[tid] = mbase + tid;
    }
    __syncthreads();

    const uint32_t sb = smem_u32(smem);

    // ---- cp.async jobs: 6 chunks/thread (2 A rows + 4 B rows, same chunk col)
    const int c8 = (tid & 7) * 16;     // byte offset within 128B row payload
    const int r0 = tid >> 3;           // 0..63
    const int tokA0 = stok[r0];
    const int tokA1 = stok[r0 + 64];
    const char* gA0 = (const char*)(g_Xh + (size_t)(tokA0 >= 0 ? tokA0 : 0) * DIM) + c8;
    const char* gA1 = (const char*)(g_Xh + (size_t)(tokA1 >= 0 ? tokA1 : 0) * DIM) + c8;
    const uint32_t szA0 = (tokA0 >= 0) ? 16u : 0u;
    const uint32_t szA1 = (tokA1 >= 0) ? 16u : 0u;
    const uint32_t soA0 = OFF_AH + r0 * ROWB + c8;
    const uint32_t soA1 = soA0 + 64 * ROWB;
    const char* gB = (const char*)(g_Wh + woff + (size_t)(nbase + r0) * DIM) + c8;
    const uint32_t soB = OFF_BH + r0 * ROWB + c8;

    // ---- warp tiling
    const int wm = (w & 3) * 32;
    const int wn = (w >> 2) * 64;
    const int lr = lane & 15;
    const int lkb = (lane >> 4) * 16;

    float acc[2][8][4];
    #pragma unroll
    for (int mi = 0; mi < 2; ++mi)
        #pragma unroll
        for (int nj = 0; nj < 8; ++nj)
            #pragma unroll
            for (int q = 0; q < 4; ++q) acc[mi][nj][q] = 0.f;

    // prologue: stages 0, 1
    #pragma unroll
    for (int s = 0; s < 2; ++s) {
        const uint32_t d = sb + s * STGB;
        const int ko = s * (BK * 2);
        CP_ASYNC16(d + soA0, gA0 + ko, szA0);
        CP_ASYNC16(d + soA1, gA1 + ko, szA1);
        #pragma unroll
        for (int tb = 0; tb < 4; ++tb)
            CP_ASYNC16(d + soB + tb * (64 * ROWB), gB + tb * (64 * DIM * 2) + ko, 16u);
        CP_COMMIT();
    }

    int rd = 0, wr = 2;
    for (int it = 0; it < KIT; ++it) {
        CP_WAIT_1();
        __syncthreads();

        if (it + 2 < KIT) {
            const uint32_t d = sb + wr * STGB;
            const int ko = (it + 2) * (BK * 2);
            CP_ASYNC16(d + soA0, gA0 + ko, szA0);
            CP_ASYNC16(d + soA1, gA1 + ko, szA1);
            #pragma unroll
            for (int tb = 0; tb < 4; ++tb)
                CP_ASYNC16(d + soB + tb * (64 * ROWB), gB + tb * (64 * DIM * 2) + ko, 16u);
        }
        CP_COMMIT();

        const uint32_t sgb = sb + rd * STGB;
        #pragma unroll
        for (int kk = 0; kk < 4; ++kk) {     // four k16 steps in BK=64
            const uint32_t kb = kk * 32 + lkb;
            uint32_t ah[2][4];
            #pragma unroll
            for (int mi = 0; mi < 2; ++mi) {
                const uint32_t ro = (uint32_t)(wm + mi * 16 + lr) * ROWB + kb;
                LDM_X4(ah[mi], sgb + OFF_AH + ro);
            }
            #pragma unroll
            for (int njp = 0; njp < 4; ++njp) {
                uint32_t bh[4];
                const uint32_t ro = (uint32_t)(wn + njp * 16 + lr) * ROWB + kb;
                LDM_X4(bh, sgb + OFF_BH + ro);
                #pragma unroll
                for (int mi = 0; mi < 2; ++mi)
                    #pragma unroll
                    for (int t = 0; t < 2; ++t)
                        MMA(acc[mi][njp * 2 + t], ah[mi], bh[t], bh[t + 2]);
            }
        }
        rd = (rd == 2) ? 0 : rd + 1;
        wr = (wr == 2) ? 0 : wr + 1;
    }

    const int gid = lane >> 2;
    const int tq = lane & 3;

    if (MODE == 1) {
        // ---- expert epilogue: relu(+bias)*p, scatter to out ----
        #pragma unroll
        for (int mi = 0; mi < 2; ++mi) {
            #pragma unroll
            for (int rh = 0; rh < 2; ++rh) {
                const int mloc = wm + mi * 16 + gid + rh * 8;
                const int tok = stok[mloc];
                if (tok < 0) continue;
                const float pt = g_p[tok];
                float* dst = C + (size_t)tok * DIM;
                #pragma unroll
                for (int nj = 0; nj < 8; ++nj) {
                    const int n = nbase + wn + nj * 8 + tq * 2;
                    float v0 = fmaxf(acc[mi][nj][rh * 2]     + bias[n], 0.f) * pt;
                    float v1 = fmaxf(acc[mi][nj][rh * 2 + 1] + bias[n + 1], 0.f) * pt;
                    *(float2*)(dst + n) = make_float2(v0, v1);
                }
            }
        }
    } else {
        // ---- gating epilogue: fused routing partials (no logit store) ----
        // stats buffers live in pipeline slot 1 region (final stage uses slot 0)
        float* st_m1 = (float*)(smem + STGB);
        float* st_m2 = st_m1 + 512;
        float* st_s  = st_m1 + 1024;
        int*   st_i1 = (int*)(st_m1 + 1536);
        int*   st_i2 = (int*)(st_m1 + 2048);
        const int wnidx = w >> 2;

        #pragma unroll
        for (int mi = 0; mi < 2; ++mi) {
            #pragma unroll
            for (int rh = 0; rh < 2; ++rh) {
                const int row = wm + mi * 16 + gid + rh * 8;
                // thread-local top2 over its 16 cols
                float m1 = -3.4e38f, m2 = -3.4e38f;
                int i1 = 0x7fffffff, i2 = 0x7fffffff;
                float vals[16];
                #pragma unroll
                for (int nj = 0; nj < 8; ++nj) {
                    #pragma unroll
                    for (int cc = 0; cc < 2; ++cc) {
                        const int n = nbase + wn + nj * 8 + tq * 2 + cc;
                        const float v = acc[mi][nj][rh * 2 + cc] + bias[n];
                        vals[nj * 2 + cc] = v;
                        if (v > m1) { m2 = m1; i2 = i1; m1 = v; i1 = n; }
                        else if (v > m2) { m2 = v; i2 = n; }
                    }
                }
                float s = 0.f;
                #pragma unroll
                for (int q = 0; q < 16; ++q) s += expf(vals[q] - m1);
                // merge across the 4 tq lanes of this row
                #pragma unroll
                for (int off = 1; off <= 2; off <<= 1) {
                    const float om1 = __shfl_xor_sync(0xffffffffu, m1, off);
                    const int   oi1 = __shfl_xor_sync(0xffffffffu, i1, off);
                    const float om2 = __shfl_xor_sync(0xffffffffu, m2, off);
                    const int   oi2 = __shfl_xor_sync(0xffffffffu, i2, off);
                    const float os  = __shfl_xor_sync(0xffffffffu, s,  off);
                    merge5(m1, i1, m2, i2, s, om1, oi1, om2, oi2, os);
                }
                if (tq == 0) {
                    const int idx = wnidx * 128 + row;
                    st_m1[idx] = m1; st_m2[idx] = m2; st_s[idx] = s;
                    st_i1[idx] = i1; st_i2[idx] = i2;
                }
            }
        }
        __syncthreads();
        if (tid < 128) {
            float m1 = st_m1[tid], m2 = st_m2[tid], s = st_s[tid];
            int i1 = st_i1[tid], i2 = st_i2[tid];
            #pragma unroll
            for (int x = 1; x < 4; ++x) {
                const int idx = x * 128 + tid;
                merge5(m1, i1, m2, i2, s,
                       st_m1[idx], st_i1[idx], st_m2[idx], st_i2[idx], st_s[idx]);
            }
            float* P = g_part + (size_t)(mbase + tid) * 32 + blockIdx.x * 8;
            P[0] = m1; P[1] = m2; P[2] = s;
            P[3] = __int_as_float(i1); P[4] = __int_as_float(i2);
        }
    }
}

// =====================================================================
// Route: merge 4 partials per token + exact fp32 rescue of close argmax.
// 1 block (64 thr) per token.
// =====================================================================
__global__ __launch_bounds__(64) void k_route(const float* __restrict__ X,
                                              const float* __restrict__ Wg,
                                              const float* __restrict__ bg) {
    const int t = blockIdx.x;
    const int tid = threadIdx.x;

    __shared__ float s_m1, s_m2, s_sum;
    __shared__ int   s_i1, s_i2, s_amb;
    __shared__ float red[4];

    if (tid == 0) {
        const float* P = g_part + (size_t)t * 32;
        float m1 = P[0], m2 = P[1], s = P[2];
        int i1 = __float_as_int(P[3]), i2 = __float_as_int(P[4]);
        #pragma unroll
        for (int x = 1; x < 4; ++x) {
            const float* Q = P + x * 8;
            merge5(m1, i1, m2, i2, s,
                   Q[0], __float_as_int(Q[3]), Q[1], __float_as_int(Q[4]), Q[2]);
        }
        s_m1 = m1; s_m2 = m2; s_sum = s; s_i1 = i1; s_i2 = i2;
        s_amb = (m1 - m2) < GAP_THRESH;
    }
    __syncthreads();

    if (s_amb) {
        const int c1 = s_i1, c2 = s_i2;
        float p1 = 0.f, p2 = 0.f;
        const float* xr = X + (size_t)t * DIM;
        for (int k = tid; k < DIM; k += 64) {
            const float xv = xr[k];
            p1 += xv * Wg[(size_t)k * DIM + c1];
            p2 += xv * Wg[(size_t)k * DIM + c2];
        }
        #pragma unroll
        for (int off = 16; off > 0; off >>= 1) {
            p1 += __shfl_down_sync(0xffffffffu, p1, off);
            p2 += __shfl_down_sync(0xffffffffu, p2, off);
        }
        const int wid = tid >> 5, lane = tid & 31;
        if (lane == 0) { red[wid] = p1; red[2 + wid] = p2; }
        __syncthreads();
        if (tid == 0) {
            const float d1 = bg[c1] + red[0] + red[1];
            const float d2 = bg[c2] + red[2] + red[3];
            if (d2 > d1 || (d2 == d1 && c2 < c1)) { s_i1 = c2; s_m1 = s_m2; }
        }
        __syncthreads();
    }

    if (tid == 0) {
        const int chosen = s_i1;
        const int ex = chosen & (NEXP - 1);
        const int pos = atomicAdd(&g_cnt[ex], 1);
        g_tok[ex * NTOK + pos] = t;
        // p = exp(l_chosen - max) / sumexp ; sum is relative to merged max
        float lmax = fmaxf(s_m1, s_m2);   // s_m1 may have been demoted by rescue
        g_p[t] = expf(s_m1 - lmax) / s_sum;
    }
}

// =====================================================================
extern "C" void kernel_launch(void* const* d_in, const int* in_sizes, int n_in,
                              void* d_out, int out_size) {
    const float* x  = (const float*)d_in[0];
    const float* Wg = (const float*)d_in[1];
    const float* bg = (const float*)d_in[2];
    const float* We = (const float*)d_in[3];
    const float* be = (const float*)d_in[4];
    float* out = (float*)d_out;

    cudaFuncSetAttribute(k_gemm<0>, cudaFuncAttributeMaxDynamicSharedMemorySize, SMEM_BYTES);
    cudaFuncSetAttribute(k_gemm<1>, cudaFuncAttributeMaxDynamicSharedMemorySize, SMEM_BYTES);

    k_init<<<1, 32>>>();
    k_split_x<<<(NTOK * DIM / 4) / 256, 256>>>(x);
    k_split_w<<<dim3(32, 32, 1 + NEXP), dim3(32, 8)>>>(Wg, We);
    k_gemm<0><<<dim3(DIM / BN, NTOK / BM), 512, SMEM_BYTES>>>(bg, nullptr);
    k_route<<<NTOK, 64>>>(x, Wg, bg);
    k_gemm<1><<<dim3(DIM / BN, NTOK / BM, NEXP), 512, SMEM_BYTES>>>(be, out);
}

// round 12
// speedup vs baseline: 2.9010x; 1.0282x over previous
#include <cuda_runtime.h>
#include <cuda_fp16.h>
#include <math.h>
#include <stdint.h>

#define DIM  1024
#define NEXP 8
#define NTOK 16384
#define BM   128
#define BN   256
#define BK   64
#define KIT  (DIM/BK)        // 16 stages
#define ROWB 144             // 64 halves (128B) + 16B pad
#define OFF_AH 0
#define OFF_BH (128*ROWB)
#define STGB   (OFF_BH + 256*ROWB)      // 55296
#define NSTG 3
#define SMEM_BYTES (NSTG*STGB)          // 165888
#define GAP_THRESH 5.0e-3f

// ---------------- device-global scratch (allocation-free) ----------------
__device__ __half g_Xh[(size_t)NTOK * DIM];
__device__ __half g_Wh[(size_t)(1 + NEXP) * DIM * DIM];   // [N][K] fp16
__device__ float  g_part[(size_t)NTOK * 32];
__device__ int    g_cnt[NEXP];
__device__ int    g_tok[NEXP * NTOK];
__device__ float  g_p[NTOK];

// ---------------- PTX helpers ----------------
static __device__ __forceinline__ uint32_t smem_u32(const void* p) {
    uint32_t a;
    asm("{ .reg .u64 t; cvta.to.shared.u64 t, %1; cvt.u32.u64 %0, t; }" : "=r"(a) : "l"(p));
    return a;
}
#define CP_ASYNC16(dst, src, sz) \
    asm volatile("cp.async.cg.shared.global [%0], [%1], 16, %2;" \
                 :: "r"(dst), "l"(src), "r"(sz) : "memory")
#define CP_COMMIT() asm volatile("cp.async.commit_group;" ::: "memory")
#define CP_WAIT_1() asm volatile("cp.async.wait_group 1;" ::: "memory")

#define LDM_X4(r, addr) \
    asm volatile("ldmatrix.sync.aligned.m8n8.x4.shared.b16 {%0,%1,%2,%3}, [%4];" \
                 : "=r"((r)[0]), "=r"((r)[1]), "=r"((r)[2]), "=r"((r)[3]) : "r"(addr))

#define MMA(d, a, b0_, b1_) \
    asm volatile("mma.sync.aligned.m16n8k16.row.col.f32.f16.f16.f32 " \
                 "{%0,%1,%2,%3},{%4,%5,%6,%7},{%8,%9},{%0,%1,%2,%3};" \
                 : "+f"((d)[0]), "+f"((d)[1]), "+f"((d)[2]), "+f"((d)[3]) \
                 : "r"((a)[0]), "r"((a)[1]), "r"((a)[2]), "r"((a)[3]), \
                   "r"(b0_), "r"(b1_))

// ---- top-2 merge (first-index tie-break, jnp.argmax compatible) ----
static __device__ __forceinline__ void merge_top2(float& m1, int& i1, float& m2, int& i2,
                                                  float om1, int oi1, float om2, int oi2) {
    if (om1 > m1 || (om1 == m1 && oi1 < i1)) {
        float c = m1; int ci = i1;
        m1 = om1; i1 = oi1;
        if (om2 > c || (om2 == c && oi2 < ci)) { m2 = om2; i2 = oi2; }
        else                                   { m2 = c;   i2 = ci;  }
    } else {
        if (om1 > m2 || (om1 == m2 && oi1 < i2)) { m2 = om1; i2 = oi1; }
    }
}
static __device__ __forceinline__ void merge5(float& m1, int& i1, float& m2, int& i2, float& s,
                                              float om1, int oi1, float om2, int oi2, float os) {
    const float M = fmaxf(m1, om1);
    s = s * expf(m1 - M) + os * expf(om1 - M);
    merge_top2(m1, i1, m2, i2, om1, oi1, om2, oi2);
}

// =====================================================================
// Prep: blocks [0,1024) transpose Wg -> g_Wh[z=0]; blocks [1024, 17408)
// convert x -> g_Xh. Block 0 also resets expert counters. 256 threads.
// =====================================================================
#define NBLK_WG 1024
#define NBLK_X  (NTOK * DIM / 4 / 256)   // 16384
__global__ __launch_bounds__(256) void k_prep(const float* __restrict__ X,
                                              const float* __restrict__ Wg) {
    const int id = blockIdx.x;
    const int tid = threadIdx.x;
    if (id == 0 && tid < NEXP) g_cnt[tid] = 0;

    if (id < NBLK_WG) {
        __shared__ float t[32][33];
        const int bx = id & 31, by = id >> 5;
        const int tx = tid & 31, ty = tid >> 5;   // 8 rows/iter
        #pragma unroll
        for (int i = 0; i < 32; i += 8)
            t[ty + i][tx] = Wg[(size_t)(by * 32 + ty + i) * DIM + bx * 32 + tx];
        __syncthreads();
        #pragma unroll
        for (int i = 0; i < 32; i += 8)
            g_Wh[(size_t)(bx * 32 + ty + i) * DIM + by * 32 + tx] =
                __float2half_rn(t[tx][ty + i]);
    } else {
        const size_t i = (size_t)(id - NBLK_WG) * 256 + tid;   // float4 index
        float4 v = ((const float4*)X)[i];
        ((__half2*)g_Xh)[2 * i]     = __halves2half2(__float2half_rn(v.x), __float2half_rn(v.y));
        ((__half2*)g_Xh)[2 * i + 1] = __halves2half2(__float2half_rn(v.z), __float2half_rn(v.w));
    }
}

// =====================================================================
// fp16 GEMM via mma.sync (fp32 acc), BK=64, 3-stage cp.async pipeline.
// 512 threads = 16 warps as 4(m) x 4(n); warp tile 32x64; block 128x256.
// MODE 0: gating -> per-token routing partials (top2 + sumexp)
// MODE 1: expert -> out = relu(x@We[e] + be[e]) * p   (rows gathered)
// =====================================================================
template <int MODE>
__global__ __launch_bounds__(512, 1) void k_gemm(const float* __restrict__ bias_,
                                                 float* __restrict__ C) {
    extern __shared__ char smem[];
    __shared__ int stok[BM];

    const int tid = threadIdx.x;
    const int lane = tid & 31;
    const int w = tid >> 5;
    const int mbase = blockIdx.y * BM;
    const int nbase = blockIdx.x * BN;

    const float* bias = bias_;
    size_t woff = 0;
    if (MODE == 1) {
        const int e = blockIdx.z;
        const int cnt = g_cnt[e];
        if (mbase >= cnt) return;
        woff = (size_t)(1 + e) * DIM * DIM;
        bias = bias_ + e * DIM;
        if (tid < BM) {
            const int i = mbase + tid;
            stok[tid] = (i < cnt) ? g_tok[e * NTOK + i] : -1;
        }
    } else {
        if (tid < BM) stok[tid] = mbase + tid;
    }
    __syncthreads();

    const uint32_t sb = smem_u32(smem);

    const int c8 = (tid & 7) * 16;
    const int r0 = tid >> 3;
    const int tokA0 = stok[r0];
    const int tokA1 = stok[r0 + 64];
    const char* gA0 = (const char*)(g_Xh + (size_t)(tokA0 >= 0 ? tokA0 : 0) * DIM) + c8;
    const char* gA1 = (const char*)(g_Xh + (size_t)(tokA1 >= 0 ? tokA1 : 0) * DIM) + c8;
    const uint32_t szA0 = (tokA0 >= 0) ? 16u : 0u;
    const uint32_t szA1 = (tokA1 >= 0) ? 16u : 0u;
    const uint32_t soA0 = OFF_AH + r0 * ROWB + c8;
    const uint32_t soA1 = soA0 + 64 * ROWB;
    const char* gB = (const char*)(g_Wh + woff + (size_t)(nbase + r0) * DIM) + c8;
    const uint32_t soB = OFF_BH + r0 * ROWB + c8;

    const int wm = (w & 3) * 32;
    const int wn = (w >> 2) * 64;
    const int lr = lane & 15;
    const int lkb = (lane >> 4) * 16;

    float acc[2][8][4];
    #pragma unroll
    for (int mi = 0; mi < 2; ++mi)
        #pragma unroll
        for (int nj = 0; nj < 8; ++nj)
            #pragma unroll
            for (int q = 0; q < 4; ++q) acc[mi][nj][q] = 0.f;

    #pragma unroll
    for (int s = 0; s < 2; ++s) {
        const uint32_t d = sb + s * STGB;
        const int ko = s * (BK * 2);
        CP_ASYNC16(d + soA0, gA0 + ko, szA0);
        CP_ASYNC16(d + soA1, gA1 + ko, szA1);
        #pragma unroll
        for (int tb = 0; tb < 4; ++tb)
            CP_ASYNC16(d + soB + tb * (64 * ROWB), gB + tb * (64 * DIM * 2) + ko, 16u);
        CP_COMMIT();
    }

    int rd = 0, wr = 2;
    for (int it = 0; it < KIT; ++it) {
        CP_WAIT_1();
        __syncthreads();

        if (it + 2 < KIT) {
            const uint32_t d = sb + wr * STGB;
            const int ko = (it + 2) * (BK * 2);
            CP_ASYNC16(d + soA0, gA0 + ko, szA0);
            CP_ASYNC16(d + soA1, gA1 + ko, szA1);
            #pragma unroll
            for (int tb = 0; tb < 4; ++tb)
                CP_ASYNC16(d + soB + tb * (64 * ROWB), gB + tb * (64 * DIM * 2) + ko, 16u);
        }
        CP_COMMIT();

        const uint32_t sgb = sb + rd * STGB;
        #pragma unroll
        for (int kk = 0; kk < 4; ++kk) {
            const uint32_t kb = kk * 32 + lkb;
            uint32_t ah[2][4];
            #pragma unroll
            for (int mi = 0; mi < 2; ++mi) {
                const uint32_t ro = (uint32_t)(wm + mi * 16 + lr) * ROWB + kb;
                LDM_X4(ah[mi], sgb + OFF_AH + ro);
            }
            #pragma unroll
            for (int njp = 0; njp < 4; ++njp) {
                uint32_t bh[4];
                const uint32_t ro = (uint32_t)(wn + njp * 16 + lr) * ROWB + kb;
                LDM_X4(bh, sgb + OFF_BH + ro);
                #pragma unroll
                for (int mi = 0; mi < 2; ++mi)
                    #pragma unroll
                    for (int t = 0; t < 2; ++t)
                        MMA(acc[mi][njp * 2 + t], ah[mi], bh[t], bh[t + 2]);
            }
        }
        rd = (rd == 2) ? 0 : rd + 1;
        wr = (wr == 2) ? 0 : wr + 1;
    }

    const int gid = lane >> 2;
    const int tq = lane & 3;

    if (MODE == 1) {
        #pragma unroll
        for (int mi = 0; mi < 2; ++mi) {
            #pragma unroll
            for (int rh = 0; rh < 2; ++rh) {
                const int mloc = wm + mi * 16 + gid + rh * 8;
                const int tok = stok[mloc];
                if (tok < 0) continue;
                const float pt = g_p[tok];
                float* dst = C + (size_t)tok * DIM;
                #pragma unroll
                for (int nj = 0; nj < 8; ++nj) {
                    const int n = nbase + wn + nj * 8 + tq * 2;
                    float v0 = fmaxf(acc[mi][nj][rh * 2]     + bias[n], 0.f) * pt;
                    float v1 = fmaxf(acc[mi][nj][rh * 2 + 1] + bias[n + 1], 0.f) * pt;
                    *(float2*)(dst + n) = make_float2(v0, v1);
                }
            }
        }
    } else {
        // ---- gating epilogue: fused routing partials ----
        float* st_m1 = (float*)(smem + STGB);
        float* st_m2 = st_m1 + 512;
        float* st_s  = st_m1 + 1024;
        int*   st_i1 = (int*)(st_m1 + 1536);
        int*   st_i2 = (int*)(st_m1 + 2048);
        const int wnidx = w >> 2;

        #pragma unroll
        for (int mi = 0; mi < 2; ++mi) {
            #pragma unroll
            for (int rh = 0; rh < 2; ++rh) {
                const int row = wm + mi * 16 + gid + rh * 8;
                float m1 = -3.4e38f, m2 = -3.4e38f;
                int i1 = 0x7fffffff, i2 = 0x7fffffff;
                float vals[16];
                #pragma unroll
                for (int nj = 0; nj < 8; ++nj) {
                    #pragma unroll
                    for (int cc = 0; cc < 2; ++cc) {
                        const int n = nbase + wn + nj * 8 + tq * 2 + cc;
                        const float v = acc[mi][nj][rh * 2 + cc] + bias[n];
                        vals[nj * 2 + cc] = v;
                        if (v > m1) { m2 = m1; i2 = i1; m1 = v; i1 = n; }
                        else if (v > m2) { m2 = v; i2 = n; }
                    }
                }
                float s = 0.f;
                #pragma unroll
                for (int q = 0; q < 16; ++q) s += expf(vals[q] - m1);
                #pragma unroll
                for (int off = 1; off <= 2; off <<= 1) {
                    const float om1 = __shfl_xor_sync(0xffffffffu, m1, off);
                    const int   oi1 = __shfl_xor_sync(0xffffffffu, i1, off);
                    const float om2 = __shfl_xor_sync(0xffffffffu, m2, off);
                    const int   oi2 = __shfl_xor_sync(0xffffffffu, i2, off);
                    const float os  = __shfl_xor_sync(0xffffffffu, s,  off);
                    merge5(m1, i1, m2, i2, s, om1, oi1, om2, oi2, os);
                }
                if (tq == 0) {
                    const int idx = wnidx * 128 + row;
                    st_m1[idx] = m1; st_m2[idx] = m2; st_s[idx] = s;
                    st_i1[idx] = i1; st_i2[idx] = i2;
                }
            }
        }
        __syncthreads();
        if (tid < 128) {
            float m1 = st_m1[tid], m2 = st_m2[tid], s = st_s[tid];
            int i1 = st_i1[tid], i2 = st_i2[tid];
            #pragma unroll
            for (int x = 1; x < 4; ++x) {
                const int idx = x * 128 + tid;
                merge5(m1, i1, m2, i2, s,
                       st_m1[idx], st_i1[idx], st_m2[idx], st_i2[idx], st_s[idx]);
            }
            float* P = g_part + (size_t)(mbase + tid) * 32 + blockIdx.x * 8;
            P[0] = m1; P[1] = m2; P[2] = s;
            P[3] = __int_as_float(i1); P[4] = __int_as_float(i2);
        }
    }
}

// =====================================================================
// Route + We transpose in ONE kernel. 64 threads/block.
// blocks [0, NTOK): route token t. blocks [NTOK, NTOK+8192): transpose
// We expert tiles into g_Wh[z=1..8] (fills idle SMs under route's grid).
// =====================================================================
__global__ __launch_bounds__(64) void k_route_we(const float* __restrict__ X,
                                                 const float* __restrict__ Wg,
                                                 const float* __restrict__ bg,
                                                 const float* __restrict__ We) {
    const int tid = threadIdx.x;

    if (blockIdx.x >= NTOK) {
        // ---- We transpose tile ----
        __shared__ float t[32][33];
        const int zz = blockIdx.x - NTOK;
        const int z = zz >> 10;              // expert 0..7
        const int tile = zz & 1023;
        const int bx = tile & 31, by = tile >> 5;
        const float* src = We + (size_t)z * DIM * DIM;
        __half* dh = g_Wh + (size_t)(1 + z) * DIM * DIM;
        const int tx = tid & 31, ty0 = tid >> 5;   // 2 rows/iter
        #pragma unroll
        for (int i = ty0; i < 32; i += 2)
            t[i][tx] = src[(size_t)(by * 32 + i) * DIM + bx * 32 + tx];
        __syncthreads();
        #pragma unroll
        for (int i = ty0; i < 32; i += 2)
            dh[(size_t)(bx * 32 + i) * DIM + by * 32 + tx] = __float2half_rn(t[tx][i]);
        return;
    }

    // ---- route token ----
    const int t = blockIdx.x;
    __shared__ float s_m1, s_m2, s_sum;
    __shared__ int   s_i1, s_i2, s_amb;
    __shared__ float red[4];

    if (tid == 0) {
        const float* P = g_part + (size_t)t * 32;
        float m1 = P[0], m2 = P[1], s = P[2];
        int i1 = __float_as_int(P[3]), i2 = __float_as_int(P[4]);
        #pragma unroll
        for (int x = 1; x < 4; ++x) {
            const float* Q = P + x * 8;
            merge5(m1, i1, m2, i2, s,
                   Q[0], __float_as_int(Q[3]), Q[1], __float_as_int(Q[4]), Q[2]);
        }
        s_m1 = m1; s_m2 = m2; s_sum = s; s_i1 = i1; s_i2 = i2;
        s_amb = (m1 - m2) < GAP_THRESH;
    }
    __syncthreads();

    if (s_amb) {
        const int c1 = s_i1, c2 = s_i2;
        float p1 = 0.f, p2 = 0.f;
        const float* xr = X + (size_t)t * DIM;
        for (int k = tid; k < DIM; k += 64) {
            const float xv = xr[k];
            p1 += xv * Wg[(size_t)k * DIM + c1];
            p2 += xv * Wg[(size_t)k * DIM + c2];
        }
        #pragma unroll
        for (int off = 16; off > 0; off >>= 1) {
            p1 += __shfl_down_sync(0xffffffffu, p1, off);
            p2 += __shfl_down_sync(0xffffffffu, p2, off);
        }
        const int wid = tid >> 5, lane = tid & 31;
        if (lane == 0) { red[wid] = p1; red[2 + wid] = p2; }
        __syncthreads();
        if (tid == 0) {
            const float d1 = bg[c1] + red[0] + red[1];
            const float d2 = bg[c2] + red[2] + red[3];
            if (d2 > d1 || (d2 == d1 && c2 < c1)) { s_i1 = c2; s_m1 = s_m2; }
        }
        __syncthreads();
    }

    if (tid == 0) {
        const int chosen = s_i1;
        const int ex = chosen & (NEXP - 1);
        const int pos = atomicAdd(&g_cnt[ex], 1);
        g_tok[ex * NTOK + pos] = t;
        float lmax = fmaxf(s_m1, s_m2);
        g_p[t] = expf(s_m1 - lmax) / s_sum;
    }
}

// =====================================================================
extern "C" void kernel_launch(void* const* d_in, const int* in_sizes, int n_in,
                              void* d_out, int out_size) {
    const float* x  = (const float*)d_in[0];
    const float* Wg = (const float*)d_in[1];
    const float* bg = (const float*)d_in[2];
    const float* We = (const float*)d_in[3];
    const float* be = (const float*)d_in[4];
    float* out = (float*)d_out;

    cudaFuncSetAttribute(k_gemm<0>, cudaFuncAttributeMaxDynamicSharedMemorySize, SMEM_BYTES);
    cudaFuncSetAttribute(k_gemm<1>, cudaFuncAttributeMaxDynamicSharedMemorySize, SMEM_BYTES);

    k_prep<<<NBLK_WG + NBLK_X, 256>>>(x, Wg);
    k_gemm<0><<<dim3(DIM / BN, NTOK / BM), 512, SMEM_BYTES>>>(bg, nullptr);
    k_route_we<<<NTOK + NEXP * 1024, 64>>>(x, Wg, bg, We);
    k_gemm<1><<<dim3(DIM / BN, NTOK / BM, NEXP), 512, SMEM_BYTES>>>(be, out);
}

// round 13
// speedup vs baseline: 3.0059x; 1.0361x over previous
#include <cuda_runtime.h>
#include <cuda_fp16.h>
#include <math.h>
#include <stdint.h>

#define DIM  1024
#define NEXP 8
#define NTOK 16384
#define BM   128
#define BN   256
#define BK   64
#define KIT  (DIM/BK)        // 16 stages
#define ROWB 144             // 64 halves (128B) + 16B pad
#define OFF_AH 0
#define OFF_BH (128*ROWB)
#define STGB   (OFF_BH + 256*ROWB)      // 55296
#define NSTG 3
#define SMEM_BYTES (NSTG*STGB)          // 165888
#define GAP_THRESH 5.0e-3f
#define NROW (NTOK/BM)                  // 128 row-blocks

// ---------------- device-global scratch (allocation-free) ----------------
__device__ __half g_Xh[(size_t)NTOK * DIM];
__device__ __half g_Wh[(size_t)(1 + NEXP) * DIM * DIM];   // [N][K] fp16
__device__ float  g_part[(size_t)NTOK * 32];
__device__ int    g_cnt[NEXP];
__device__ int    g_done[NROW];
__device__ int    g_tok[NEXP * NTOK];
__device__ float  g_p[NTOK];

// ---------------- PTX helpers ----------------
static __device__ __forceinline__ uint32_t smem_u32(const void* p) {
    uint32_t a;
    asm("{ .reg .u64 t; cvta.to.shared.u64 t, %1; cvt.u32.u64 %0, t; }" : "=r"(a) : "l"(p));
    return a;
}
#define CP_ASYNC16(dst, src, sz) \
    asm volatile("cp.async.cg.shared.global [%0], [%1], 16, %2;" \
                 :: "r"(dst), "l"(src), "r"(sz) : "memory")
#define CP_COMMIT() asm volatile("cp.async.commit_group;" ::: "memory")
#define CP_WAIT_1() asm volatile("cp.async.wait_group 1;" ::: "memory")

#define LDM_X4(r, addr) \
    asm volatile("ldmatrix.sync.aligned.m8n8.x4.shared.b16 {%0,%1,%2,%3}, [%4];" \
                 : "=r"((r)[0]), "=r"((r)[1]), "=r"((r)[2]), "=r"((r)[3]) : "r"(addr))

#define MMA(d, a, b0_, b1_) \
    asm volatile("mma.sync.aligned.m16n8k16.row.col.f32.f16.f16.f32 " \
                 "{%0,%1,%2,%3},{%4,%5,%6,%7},{%8,%9},{%0,%1,%2,%3};" \
                 : "+f"((d)[0]), "+f"((d)[1]), "+f"((d)[2]), "+f"((d)[3]) \
                 : "r"((a)[0]), "r"((a)[1]), "r"((a)[2]), "r"((a)[3]), \
                   "r"(b0_), "r"(b1_))

// ---- top-2 merge (first-index tie-break, jnp.argmax compatible) ----
static __device__ __forceinline__ void merge_top2(float& m1, int& i1, float& m2, int& i2,
                                                  float om1, int oi1, float om2, int oi2) {
    if (om1 > m1 || (om1 == m1 && oi1 < i1)) {
        float c = m1; int ci = i1;
        m1 = om1; i1 = oi1;
        if (om2 > c || (om2 == c && oi2 < ci)) { m2 = om2; i2 = oi2; }
        else                                   { m2 = c;   i2 = ci;  }
    } else {
        if (om1 > m2 || (om1 == m2 && oi1 < i2)) { m2 = om1; i2 = oi1; }
    }
}
static __device__ __forceinline__ void merge5(float& m1, int& i1, float& m2, int& i2, float& s,
                                              float om1, int oi1, float om2, int oi2, float os) {
    const float M = fmaxf(m1, om1);
    s = s * expf(m1 - M) + os * expf(om1 - M);
    merge_top2(m1, i1, m2, i2, om1, oi1, om2, oi2);
}

// =====================================================================
// Prep: blocks [0,1024) transpose Wg -> g_Wh[z=0]; blocks [1024, 17408)
// convert x -> g_Xh. Block 0 also resets counters. 256 threads.
// =====================================================================
#define NBLK_WG 1024
#define NBLK_X  (NTOK * DIM / 4 / 256)   // 16384
__global__ __launch_bounds__(256) void k_prep(const float* __restrict__ X,
                                              const float* __restrict__ Wg) {
    const int id = blockIdx.x;
    const int tid = threadIdx.x;
    if (id == 0) {
        if (tid < NEXP) g_cnt[tid] = 0;
        if (tid < NROW) g_done[tid] = 0;
    }

    if (id < NBLK_WG) {
        __shared__ float t[32][33];
        const int bx = id & 31, by = id >> 5;
        const int tx = tid & 31, ty = tid >> 5;
        #pragma unroll
        for (int i = 0; i < 32; i += 8)
            t[ty + i][tx] = Wg[(size_t)(by * 32 + ty + i) * DIM + bx * 32 + tx];
        __syncthreads();
        #pragma unroll
        for (int i = 0; i < 32; i += 8)
            g_Wh[(size_t)(bx * 32 + ty + i) * DIM + by * 32 + tx] =
                __float2half_rn(t[tx][ty + i]);
    } else {
        const size_t i = (size_t)(id - NBLK_WG) * 256 + tid;
        float4 v = ((const float4*)X)[i];
        ((__half2*)g_Xh)[2 * i]     = __halves2half2(__float2half_rn(v.x), __float2half_rn(v.y));
        ((__half2*)g_Xh)[2 * i + 1] = __halves2half2(__float2half_rn(v.z), __float2half_rn(v.w));
    }
}

// =====================================================================
// fp16 GEMM via mma.sync (fp32 acc), BK=64, 3-stage cp.async pipeline.
// 512 threads = 16 warps as 4(m) x 4(n); warp tile 32x64; block 128x256.
// MODE 0: gating; grid (4, 128+32):
//   y <  128 : GEMM tile -> partials; last CTA of each row merges, rescues,
//              and appends routing (fused k_route).
//   y >= 128 : We transpose CTAs (fill tail wave).
// MODE 1: expert -> out = relu(x@We[e] + be[e]) * p   (rows gathered)
// =====================================================================
template <int MODE>
__global__ __launch_bounds__(512, 1) void k_gemm(const float* __restrict__ bias_,
                                                 float* __restrict__ C,
                                                 const float* __restrict__ X32,
                                                 const float* __restrict__ Wg32,
                                                 const float* __restrict__ We32) {
    extern __shared__ char smem[];
    __shared__ int stok[BM];

    const int tid = threadIdx.x;
    const int lane = tid & 31;
    const int w = tid >> 5;

    // ================= We transpose CTAs (MODE 0, y >= 128) ================
    if (MODE == 0 && blockIdx.y >= NROW) {
        const int c_ = (blockIdx.y - NROW) * 4 + blockIdx.x;   // 0..127
        const int e = c_ >> 4;
        const int c0 = (c_ & 15) * 64;          // output-row (src-col) stripe
        const float* src = We32 + (size_t)e * DIM * DIM;       // [K][N]
        __half* dst = g_Wh + (size_t)(1 + e) * DIM * DIM;      // [N][K]
        float* sbuf = (float*)smem;             // [64][65]
        const int rowt = tid >> 3;              // 0..63
        const int colt = (tid & 7) * 8;         // 0..56
        for (int r0 = 0; r0 < DIM; r0 += 64) {
            float4 v0 = *(const float4*)&src[(size_t)(r0 + rowt) * DIM + c0 + colt];
            float4 v1 = *(const float4*)&src[(size_t)(r0 + rowt) * DIM + c0 + colt + 4];
            __syncthreads();
            float* dr = &sbuf[rowt * 65 + colt];
            dr[0] = v0.x; dr[1] = v0.y; dr[2] = v0.z; dr[3] = v0.w;
            dr[4] = v1.x; dr[5] = v1.y; dr[6] = v1.z; dr[7] = v1.w;
            __syncthreads();
            __half tmp[8];
            #pragma unroll
            for (int j = 0; j < 8; ++j)
                tmp[j] = __float2half_rn(sbuf[(colt + j) * 65 + rowt]);
            *(uint4*)&dst[(size_t)(c0 + rowt) * DIM + r0 + colt] = *(uint4*)tmp;
        }
        return;
    }

    const int mbase = blockIdx.y * BM;
    const int nbase = blockIdx.x * BN;

    const float* bias = bias_;
    size_t woff = 0;
    if (MODE == 1) {
        const int e = blockIdx.z;
        const int cnt = g_cnt[e];
        if (mbase >= cnt) return;
        woff = (size_t)(1 + e) * DIM * DIM;
        bias = bias_ + e * DIM;
        if (tid < BM) {
            const int i = mbase + tid;
            stok[tid] = (i < cnt) ? g_tok[e * NTOK + i] : -1;
        }
    } else {
        if (tid < BM) stok[tid] = mbase + tid;
    }
    __syncthreads();

    const uint32_t sb = smem_u32(smem);

    const int c8 = (tid & 7) * 16;
    const int r0_ = tid >> 3;
    const int tokA0 = stok[r0_];
    const int tokA1 = stok[r0_ + 64];
    const char* gA0 = (const char*)(g_Xh + (size_t)(tokA0 >= 0 ? tokA0 : 0) * DIM) + c8;
    const char* gA1 = (const char*)(g_Xh + (size_t)(tokA1 >= 0 ? tokA1 : 0) * DIM) + c8;
    const uint32_t szA0 = (tokA0 >= 0) ? 16u : 0u;
    const uint32_t szA1 = (tokA1 >= 0) ? 16u : 0u;
    const uint32_t soA0 = OFF_AH + r0_ * ROWB + c8;
    const uint32_t soA1 = soA0 + 64 * ROWB;
    const char* gB = (const char*)(g_Wh + woff + (size_t)(nbase + r0_) * DIM) + c8;
    const uint32_t soB = OFF_BH + r0_ * ROWB + c8;

    const int wm = (w & 3) * 32;
    const int wn = (w >> 2) * 64;
    const int lr = lane & 15;
    const int lkb = (lane >> 4) * 16;

    float acc[2][8][4];
    #pragma unroll
    for (int mi = 0; mi < 2; ++mi)
        #pragma unroll
        for (int nj = 0; nj < 8; ++nj)
            #pragma unroll
            for (int q = 0; q < 4; ++q) acc[mi][nj][q] = 0.f;

    #pragma unroll
    for (int s = 0; s < 2; ++s) {
        const uint32_t d = sb + s * STGB;
        const int ko = s * (BK * 2);
        CP_ASYNC16(d + soA0, gA0 + ko, szA0);
        CP_ASYNC16(d + soA1, gA1 + ko, szA1);
        #pragma unroll
        for (int tb = 0; tb < 4; ++tb)
            CP_ASYNC16(d + soB + tb * (64 * ROWB), gB + tb * (64 * DIM * 2) + ko, 16u);
        CP_COMMIT();
    }

    int rd = 0, wr = 2;
    for (int it = 0; it < KIT; ++it) {
        CP_WAIT_1();
        __syncthreads();

        if (it + 2 < KIT) {
            const uint32_t d = sb + wr * STGB;
            const int ko = (it + 2) * (BK * 2);
            CP_ASYNC16(d + soA0, gA0 + ko, szA0);
            CP_ASYNC16(d + soA1, gA1 + ko, szA1);
            #pragma unroll
            for (int tb = 0; tb < 4; ++tb)
                CP_ASYNC16(d + soB + tb * (64 * ROWB), gB + tb * (64 * DIM * 2) + ko, 16u);
        }
        CP_COMMIT();

        const uint32_t sgb = sb + rd * STGB;
        #pragma unroll
        for (int kk = 0; kk < 4; ++kk) {
            const uint32_t kb = kk * 32 + lkb;
            uint32_t ah[2][4];
            #pragma unroll
            for (int mi = 0; mi < 2; ++mi) {
                const uint32_t ro = (uint32_t)(wm + mi * 16 + lr) * ROWB + kb;
                LDM_X4(ah[mi], sgb + OFF_AH + ro);
            }
            #pragma unroll
            for (int njp = 0; njp < 4; ++njp) {
                uint32_t bh[4];
                const uint32_t ro = (uint32_t)(wn + njp * 16 + lr) * ROWB + kb;
                LDM_X4(bh, sgb + OFF_BH + ro);
                #pragma unroll
                for (int mi = 0; mi < 2; ++mi)
                    #pragma unroll
                    for (int t = 0; t < 2; ++t)
                        MMA(acc[mi][njp * 2 + t], ah[mi], bh[t], bh[t + 2]);
            }
        }
        rd = (rd == 2) ? 0 : rd + 1;
        wr = (wr == 2) ? 0 : wr + 1;
    }

    const int gid = lane >> 2;
    const int tq = lane & 3;

    if (MODE == 1) {
        #pragma unroll
        for (int mi = 0; mi < 2; ++mi) {
            #pragma unroll
            for (int rh = 0; rh < 2; ++rh) {
                const int mloc = wm + mi * 16 + gid + rh * 8;
                const int tok = stok[mloc];
                if (tok < 0) continue;
                const float pt = g_p[tok];
                float* dst = C + (size_t)tok * DIM;
                #pragma unroll
                for (int nj = 0; nj < 8; ++nj) {
                    const int n = nbase + wn + nj * 8 + tq * 2;
                    float v0 = fmaxf(acc[mi][nj][rh * 2]     + bias[n], 0.f) * pt;
                    float v1 = fmaxf(acc[mi][nj][rh * 2 + 1] + bias[n + 1], 0.f) * pt;
                    *(float2*)(dst + n) = make_float2(v0, v1);
                }
            }
        }
        return;
    }

    // ================= gating epilogue: partials =================
    {
        float* st_m1 = (float*)(smem + STGB);
        float* st_m2 = st_m1 + 512;
        float* st_s  = st_m1 + 1024;
        int*   st_i1 = (int*)(st_m1 + 1536);
        int*   st_i2 = (int*)(st_m1 + 2048);
        const int wnidx = w >> 2;

        #pragma unroll
        for (int mi = 0; mi < 2; ++mi) {
            #pragma unroll
            for (int rh = 0; rh < 2; ++rh) {
                const int row = wm + mi * 16 + gid + rh * 8;
                float m1 = -3.4e38f, m2 = -3.4e38f;
                int i1 = 0x7fffffff, i2 = 0x7fffffff;
                float vals[16];
                #pragma unroll
                for (int nj = 0; nj < 8; ++nj) {
                    #pragma unroll
                    for (int cc = 0; cc < 2; ++cc) {
                        const int n = nbase + wn + nj * 8 + tq * 2 + cc;
                        const float v = acc[mi][nj][rh * 2 + cc] + bias[n];
                        vals[nj * 2 + cc] = v;
                        if (v > m1) { m2 = m1; i2 = i1; m1 = v; i1 = n; }
                        else if (v > m2) { m2 = v; i2 = n; }
                    }
                }
                float s = 0.f;
                #pragma unroll
                for (int q = 0; q < 16; ++q) s += expf(vals[q] - m1);
                #pragma unroll
                for (int off = 1; off <= 2; off <<= 1) {
                    const float om1 = __shfl_xor_sync(0xffffffffu, m1, off);
                    const int   oi1 = __shfl_xor_sync(0xffffffffu, i1, off);
                    const float om2 = __shfl_xor_sync(0xffffffffu, m2, off);
                    const int   oi2 = __shfl_xor_sync(0xffffffffu, i2, off);
                    const float os  = __shfl_xor_sync(0xffffffffu, s,  off);
                    merge5(m1, i1, m2, i2, s, om1, oi1, om2, oi2, os);
                }
                if (tq == 0) {
                    const int idx = wnidx * 128 + row;
                    st_m1[idx] = m1; st_m2[idx] = m2; st_s[idx] = s;
                    st_i1[idx] = i1; st_i2[idx] = i2;
                }
            }
        }
        __syncthreads();
        if (tid < 128) {
            float m1 = st_m1[tid], m2 = st_m2[tid], s = st_s[tid];
            int i1 = st_i1[tid], i2 = st_i2[tid];
            #pragma unroll
            for (int x = 1; x < 4; ++x) {
                const int idx = x * 128 + tid;
                merge5(m1, i1, m2, i2, s,
                       st_m1[idx], st_i1[idx], st_m2[idx], st_i2[idx], st_s[idx]);
            }
            float* P = g_part + (size_t)(mbase + tid) * 32 + blockIdx.x * 8;
            P[0] = m1; P[1] = m2; P[2] = s;
            P[3] = __int_as_float(i1); P[4] = __int_as_float(i2);
        }
    }

    // ================= fused route: last CTA of this row-block =============
    __shared__ int s_last;
    __syncthreads();          // partial STGs issued by tid<128 are done program-order
    if (tid == 0) {
        __threadfence();
        const int v = atomicAdd(&g_done[blockIdx.y], 1);
        s_last = (v == 3);
    }
    __syncthreads();
    if (!s_last) return;

    __shared__ float r_m1[128], r_m2[128], r_sum[128];
    __shared__ int   r_i1[128], r_i2[128];
    __shared__ int   amb_list[128];
    __shared__ int   amb_cnt;
    if (tid == 0) amb_cnt = 0;
    __syncthreads();

    if (tid < 128) {
        const int t = mbase + tid;
        const float* P = g_part + (size_t)t * 32;
        float m1 = P[0], m2 = P[1], s = P[2];
        int i1 = __float_as_int(P[3]), i2 = __float_as_int(P[4]);
        #pragma unroll
        for (int x = 1; x < 4; ++x) {
            const float* Q = P + x * 8;
            merge5(m1, i1, m2, i2, s,
                   Q[0], __float_as_int(Q[3]), Q[1], __float_as_int(Q[4]), Q[2]);
        }
        r_m1[tid] = m1; r_m2[tid] = m2; r_sum[tid] = s;
        r_i1[tid] = i1; r_i2[tid] = i2;
        if ((m1 - m2) < GAP_THRESH) {
            const int p = atomicAdd(&amb_cnt, 1);
            amb_list[p] = tid;
        }
    }
    __syncthreads();

    // rescue: one warp per ambiguous token
    for (int a = w; a < amb_cnt; a += 16) {
        const int li = amb_list[a];
        const int t = mbase + li;
        const int c1 = r_i1[li], c2 = r_i2[li];
        float p1 = 0.f, p2 = 0.f;
        const float* xr = X32 + (size_t)t * DIM;
        for (int k = lane; k < DIM; k += 32) {
            const float xv = xr[k];
            p1 += xv * Wg32[(size_t)k * DIM + c1];
            p2 += xv * Wg32[(size_t)k * DIM + c2];
        }
        #pragma unroll
        for (int off = 16; off > 0; off >>= 1) {
            p1 += __shfl_down_sync(0xffffffffu, p1, off);
            p2 += __shfl_down_sync(0xffffffffu, p2, off);
        }
        if (lane == 0) {
            const float d1 = bias[c1] + p1;   // bias == bg in MODE 0
            const float d2 = bias[c2] + p2;
            if (d2 > d1 || (d2 == d1 && c2 < c1)) { r_i1[li] = c2; r_m1[li] = r_m2[li]; }
        }
    }
    __syncthreads();

    if (tid < 128) {
        const int t = mbase + tid;
        const int chosen = r_i1[tid];
        const int ex = chosen & (NEXP - 1);
        const int pos = atomicAdd(&g_cnt[ex], 1);
        g_tok[ex * NTOK + pos] = t;
        const float lmax = fmaxf(r_m1[tid], r_m2[tid]);
        g_p[t] = expf(r_m1[tid] - lmax) / r_sum[tid];
    }
}

// =====================================================================
extern "C" void kernel_launch(void* const* d_in, const int* in_sizes, int n_in,
                              void* d_out, int out_size) {
    const float* x  = (const float*)d_in[0];
    const float* Wg = (const float*)d_in[1];
    const float* bg = (const float*)d_in[2];
    const float* We = (const float*)d_in[3];
    const float* be = (const float*)d_in[4];
    float* out = (float*)d_out;

    cudaFuncSetAttribute(k_gemm<0>, cudaFuncAttributeMaxDynamicSharedMemorySize, SMEM_BYTES);
    cudaFuncSetAttribute(k_gemm<1>, cudaFuncAttributeMaxDynamicSharedMemorySize, SMEM_BYTES);

    k_prep<<<NBLK_WG + NBLK_X, 256>>>(x, Wg);
    k_gemm<0><<<dim3(DIM / BN, NROW + 32), 512, SMEM_BYTES>>>(bg, nullptr, x, Wg, We);
    k_gemm<1><<<dim3(DIM / BN, NROW, NEXP), 512, SMEM_BYTES>>>(be, out, nullptr, nullptr, nullptr);
}